// round 11
// baseline (speedup 1.0000x reference)
#include <cuda_runtime.h>
#include <cuda_bf16.h>
#include <cstdint>

#define BB 32
#define NI 1024
#define DIN 1024
#define NOUT 64
#define DOUT 1024

// ---------------- device scratch ----------------
__device__ float g_faT[NI * BB];              // f_a transposed [i][b]
__device__ float g_xout0[BB * NOUT * DOUT];   // iter-0 output [b][j][h]
__device__ float g_pred[BB * NOUT * DIN];     // pred [b][j][d]
__device__ float g_phi1[BB * NI * NOUT];      // phi iter-1 [b][i][j]
__device__ float g_phiT[NOUT * NI * BB];      // phi transposed [j][i][b]
__device__ float g_ppart[4][BB * NOUT * DIN]; // k_pred split-K partials
__device__ float g_spart[2][BB * NI * NOUT];  // k_sim split-K S partials

// ---------------- mma helpers ----------------
__device__ __forceinline__ uint32_t smem_u32(const void* p) {
    return (uint32_t)__cvta_generic_to_shared(p);
}
__device__ __forceinline__ void ldsm4(uint32_t& r0, uint32_t& r1, uint32_t& r2,
                                      uint32_t& r3, uint32_t a) {
    asm volatile("ldmatrix.sync.aligned.m8n8.x4.shared.b16 {%0,%1,%2,%3}, [%4];"
                 : "=r"(r0), "=r"(r1), "=r"(r2), "=r"(r3) : "r"(a));
}
__device__ __forceinline__ void ldsm4t(uint32_t& r0, uint32_t& r1, uint32_t& r2,
                                       uint32_t& r3, uint32_t a) {
    asm volatile("ldmatrix.sync.aligned.m8n8.x4.trans.shared.b16 {%0,%1,%2,%3}, [%4];"
                 : "=r"(r0), "=r"(r1), "=r"(r2), "=r"(r3) : "r"(a));
}
__device__ __forceinline__ void mma_bf16(float* c, const uint32_t* a,
                                         uint32_t b0, uint32_t b1) {
    asm volatile("mma.sync.aligned.m16n8k16.row.col.f32.bf16.bf16.f32 "
                 "{%0,%1,%2,%3}, {%4,%5,%6,%7}, {%8,%9}, {%0,%1,%2,%3};"
                 : "+f"(c[0]), "+f"(c[1]), "+f"(c[2]), "+f"(c[3])
                 : "r"(a[0]), "r"(a[1]), "r"(a[2]), "r"(a[3]), "r"(b0), "r"(b1));
}
__device__ __forceinline__ uint32_t packbf(__nv_bfloat16 a, __nv_bfloat16 b) {
    return (uint32_t)__bfloat16_as_ushort(a) | ((uint32_t)__bfloat16_as_ushort(b) << 16);
}
__device__ __forceinline__ void cvt_split(float4 v, uint2& hi, uint2& lo) {
    __nv_bfloat16 hx = __float2bfloat16(v.x), hy = __float2bfloat16(v.y);
    __nv_bfloat16 hz = __float2bfloat16(v.z), hw = __float2bfloat16(v.w);
    __nv_bfloat16 lx = __float2bfloat16(v.x - __bfloat162float(hx));
    __nv_bfloat16 ly = __float2bfloat16(v.y - __bfloat162float(hy));
    __nv_bfloat16 lz = __float2bfloat16(v.z - __bfloat162float(hz));
    __nv_bfloat16 lw = __float2bfloat16(v.w - __bfloat162float(hw));
    hi.x = packbf(hx, hy); hi.y = packbf(hz, hw);
    lo.x = packbf(lx, ly); lo.y = packbf(lz, lw);
}

// ---------------- K1: f_a = sigmoid(x . W_A + b_A) -> g_faT[i][b] ---------
__global__ __launch_bounds__(256) void k_fa(const float* __restrict__ x,
                                            const float* __restrict__ WA,
                                            const float* __restrict__ bA) {
    const int row = blockIdx.x * 8 + (threadIdx.x >> 5);
    const int lane = threadIdx.x & 31;
    const float4* xr = reinterpret_cast<const float4*>(x) + (size_t)row * (DIN / 4);
    const float4* w4 = reinterpret_cast<const float4*>(WA);
    float s = 0.f;
#pragma unroll
    for (int q = 0; q < 8; q++) {
        float4 xv = xr[lane + q * 32], wv = w4[lane + q * 32];
        s += xv.x * wv.x + xv.y * wv.y + xv.z * wv.z + xv.w * wv.w;
    }
#pragma unroll
    for (int o = 16; o; o >>= 1) s += __shfl_xor_sync(0xffffffffu, s, o);
    if (lane == 0) {
        const int b = row >> 10, i = row & (NI - 1);
        float tot = s + bA[0];
        g_faT[i * BB + b] = 1.f / (1.f + __expf(-tot));
    }
}

// ---------------- K2: phi0 transposed [j][i][b] ---------------------------
__global__ __launch_bounds__(256) void k_phi0(const float* __restrict__ bu,
                                              const float* __restrict__ bn) {
    const int p = blockIdx.x * 256 + threadIdx.x;
    const int j = p >> 10, i = p & (NI - 1);
    const float cu = bu[i * NOUT + j] * (1.0f / 64.0f) - bn[i * NOUT + j] * (63.0f / 64.0f);
    const float4* fa = reinterpret_cast<const float4*>(&g_faT[i * BB]);
    float4* dst = reinterpret_cast<float4*>(&g_phiT[((size_t)j * NI + i) * BB]);
#pragma unroll
    for (int q = 0; q < 8; q++) {
        float4 v = fa[q];
        dst[q] = make_float4(v.x * cu, v.y * cu, v.z * cu, v.w * cu);
    }
}

// ---------------- K3 (TENSOR, proven): out = phiT . Wm --------------------
// Grid (hb 0..7, j 0..63), 128 thr. Tile 32b x 128h, stage K=32.
#define AMP 40
#define BNP 136
template <int MODE>
__global__ __launch_bounds__(128) void k_mem(const float* __restrict__ Wm,
                                             float* __restrict__ outp) {
    const int j = blockIdx.y, hb = blockIdx.x;
    __shared__ __align__(16) uint16_t Ah[2][32][AMP], Al[2][32][AMP];
    __shared__ __align__(16) uint16_t Bh[2][32][BNP], Bl[2][32][BNP];
    const int tid = threadIdx.x, lane = tid & 31, w = tid >> 5;
    const int fr = tid >> 2, fq = tid & 3;
    const int g = lane >> 3, r = lane & 7;
    const float* WmB = Wm + (size_t)j * DOUT + (size_t)hb * 128;
    const float* Ab = g_phiT + (size_t)j * (NI * BB);

    float c[2][4][4];
#pragma unroll
    for (int mt = 0; mt < 2; mt++)
#pragma unroll
        for (int nt = 0; nt < 4; nt++)
#pragma unroll
            for (int e = 0; e < 4; e++) c[mt][nt][e] = 0.f;

    float4 bR[8], aR[2];
    {
        const float* br = WmB + (size_t)fr * (NOUT * DOUT);
#pragma unroll
        for (int q = 0; q < 8; q++)
            bR[q] = *reinterpret_cast<const float4*>(br + (size_t)(fq + q * 4) * 4);
        const float* ar = Ab + (size_t)fr * BB + fq * 8;
        aR[0] = *reinterpret_cast<const float4*>(ar);
        aR[1] = *reinterpret_cast<const float4*>(ar + 4);
    }
    {
#pragma unroll
        for (int q = 0; q < 8; q++) {
            uint2 hi, lo; cvt_split(bR[q], hi, lo);
            const int n = (fq + q * 4) * 4;
            *reinterpret_cast<uint2*>(&Bh[0][fr][n]) = hi;
            *reinterpret_cast<uint2*>(&Bl[0][fr][n]) = lo;
        }
        uint2 h0, l0, h1, l1;
        cvt_split(aR[0], h0, l0); cvt_split(aR[1], h1, l1);
        const int m = fq * 8;
        *reinterpret_cast<uint4*>(&Ah[0][fr][m]) = make_uint4(h0.x, h0.y, h1.x, h1.y);
        *reinterpret_cast<uint4*>(&Al[0][fr][m]) = make_uint4(l0.x, l0.y, l1.x, l1.y);
    }
    __syncthreads();

    const int NSTG = NI / 32;
    for (int t = 0; t < NSTG; t++) {
        const int cur = t & 1;
        const bool more = (t + 1 < NSTG);
        if (more) {
            const int i0 = (t + 1) * 32;
            const float* br = WmB + (size_t)(i0 + fr) * (NOUT * DOUT);
#pragma unroll
            for (int q = 0; q < 8; q++)
                bR[q] = *reinterpret_cast<const float4*>(br + (size_t)(fq + q * 4) * 4);
            const float* ar = Ab + (size_t)(i0 + fr) * BB + fq * 8;
            aR[0] = *reinterpret_cast<const float4*>(ar);
            aR[1] = *reinterpret_cast<const float4*>(ar + 4);
        }
#pragma unroll
        for (int kk = 0; kk < 32; kk += 16) {
            uint32_t ah[2][4], al[2][4], bh[4][2], bl[4][2];
#pragma unroll
            for (int mt = 0; mt < 2; mt++) {
                const int ak = kk + (g >> 1) * 8 + r, am = mt * 16 + (g & 1) * 8;
                ldsm4t(ah[mt][0], ah[mt][1], ah[mt][2], ah[mt][3],
                       smem_u32(&Ah[cur][ak][am]));
                ldsm4t(al[mt][0], al[mt][1], al[mt][2], al[mt][3],
                       smem_u32(&Al[cur][ak][am]));
            }
#pragma unroll
            for (int p = 0; p < 2; p++) {
                const int bk = kk + (g & 1) * 8 + r;
                const int bn = w * 32 + p * 16 + (g >> 1) * 8;
                ldsm4t(bh[2 * p][0], bh[2 * p][1], bh[2 * p + 1][0], bh[2 * p + 1][1],
                       smem_u32(&Bh[cur][bk][bn]));
                ldsm4t(bl[2 * p][0], bl[2 * p][1], bl[2 * p + 1][0], bl[2 * p + 1][1],
                       smem_u32(&Bl[cur][bk][bn]));
            }
#pragma unroll
            for (int mt = 0; mt < 2; mt++)
#pragma unroll
                for (int nt = 0; nt < 4; nt++) {
                    mma_bf16(c[mt][nt], ah[mt], bh[nt][0], bh[nt][1]);
                    mma_bf16(c[mt][nt], ah[mt], bl[nt][0], bl[nt][1]);
                    mma_bf16(c[mt][nt], al[mt], bh[nt][0], bh[nt][1]);
                }
        }
        if (more) {
            const int nxt = 1 - cur;
#pragma unroll
            for (int q = 0; q < 8; q++) {
                uint2 hi, lo; cvt_split(bR[q], hi, lo);
                const int n = (fq + q * 4) * 4;
                *reinterpret_cast<uint2*>(&Bh[nxt][fr][n]) = hi;
                *reinterpret_cast<uint2*>(&Bl[nxt][fr][n]) = lo;
            }
            uint2 h0, l0, h1, l1;
            cvt_split(aR[0], h0, l0); cvt_split(aR[1], h1, l1);
            const int m = fq * 8;
            *reinterpret_cast<uint4*>(&Ah[nxt][fr][m]) = make_uint4(h0.x, h0.y, h1.x, h1.y);
            *reinterpret_cast<uint4*>(&Al[nxt][fr][m]) = make_uint4(l0.x, l0.y, l1.x, l1.y);
        }
        __syncthreads();
    }

    float* dst = (MODE == 0) ? g_xout0 : outp;
#pragma unroll
    for (int mt = 0; mt < 2; mt++)
#pragma unroll
        for (int nt = 0; nt < 4; nt++) {
            const int m0 = mt * 16 + (lane >> 2);
            const int n = hb * 128 + w * 32 + nt * 8 + (lane & 3) * 2;
            float* o0 = dst + ((size_t)(m0 * NOUT + j)) * DOUT + n;
            *reinterpret_cast<float2*>(o0) = make_float2(c[mt][nt][0], c[mt][nt][1]);
            float* o1 = dst + ((size_t)((m0 + 8) * NOUT + j)) * DOUT + n;
            *reinterpret_cast<float2*>(o1) = make_float2(c[mt][nt][2], c[mt][nt][3]);
        }
}

// ---------------- K4 (TENSOR, split-K): pred partials ---------------------
#define PKP 24
__global__ __launch_bounds__(128) void k_predp(const float* __restrict__ WG) {
    const int nb = blockIdx.x, mb = blockIdx.y, ks = blockIdx.z;
    const int mBase = mb * 64, nBase = nb * 128, kBase = ks * 256;
    __shared__ __align__(16) uint16_t Ah[2][64][PKP], Al[2][64][PKP];
    __shared__ __align__(16) uint16_t Bh[2][16][BNP], Bl[2][16][BNP];
    const int tid = threadIdx.x, lane = tid & 31, w = tid >> 5;
    const int g = lane >> 3, r = lane & 7;
    const int fam = tid & 63, fak = (tid >> 6) * 8;
    const int fbr = tid >> 3, fbn = tid & 7;
    const int arow = lane & 15, acol = (lane >> 4) * 8;

    float c[4][4][4];
#pragma unroll
    for (int mt = 0; mt < 4; mt++)
#pragma unroll
        for (int nt = 0; nt < 4; nt++)
#pragma unroll
            for (int e = 0; e < 4; e++) c[mt][nt][e] = 0.f;

    float4 aR[2], bR[4];
#pragma unroll
    for (int q = 0; q < 2; q++)
        aR[q] = *reinterpret_cast<const float4*>(g_xout0 + (size_t)(mBase + fam) * DOUT + kBase + fak + q * 4);
#pragma unroll
    for (int q = 0; q < 4; q++)
        bR[q] = *reinterpret_cast<const float4*>(WG + (size_t)(kBase + fbr) * DIN + nBase + (size_t)(fbn + q * 8) * 4);
    {
#pragma unroll
        for (int q = 0; q < 2; q++) {
            uint2 hi, lo; cvt_split(aR[q], hi, lo);
            *reinterpret_cast<uint2*>(&Ah[0][fam][fak + q * 4]) = hi;
            *reinterpret_cast<uint2*>(&Al[0][fam][fak + q * 4]) = lo;
        }
#pragma unroll
        for (int q = 0; q < 4; q++) {
            uint2 hi, lo; cvt_split(bR[q], hi, lo);
            const int n = (fbn + q * 8) * 4;
            *reinterpret_cast<uint2*>(&Bh[0][fbr][n]) = hi;
            *reinterpret_cast<uint2*>(&Bl[0][fbr][n]) = lo;
        }
    }
    __syncthreads();

    const int NSTG = 256 / 16;
    for (int t = 0; t < NSTG; t++) {
        const int cur = t & 1;
        const bool more = (t + 1 < NSTG);
        if (more) {
            const int k0 = kBase + (t + 1) * 16;
#pragma unroll
            for (int q = 0; q < 2; q++)
                aR[q] = *reinterpret_cast<const float4*>(g_xout0 + (size_t)(mBase + fam) * DOUT + k0 + fak + q * 4);
#pragma unroll
            for (int q = 0; q < 4; q++)
                bR[q] = *reinterpret_cast<const float4*>(WG + (size_t)(k0 + fbr) * DIN + nBase + (size_t)(fbn + q * 8) * 4);
        }
        {
            uint32_t ah[4][4], al[4][4], bh[4][2], bl[4][2];
#pragma unroll
            for (int mt = 0; mt < 4; mt++) {
                ldsm4(ah[mt][0], ah[mt][1], ah[mt][2], ah[mt][3],
                      smem_u32(&Ah[cur][mt * 16 + arow][acol]));
                ldsm4(al[mt][0], al[mt][1], al[mt][2], al[mt][3],
                      smem_u32(&Al[cur][mt * 16 + arow][acol]));
            }
#pragma unroll
            for (int p = 0; p < 2; p++) {
                const int bk = (g & 1) * 8 + r;
                const int bn = w * 32 + p * 16 + (g >> 1) * 8;
                ldsm4t(bh[2 * p][0], bh[2 * p][1], bh[2 * p + 1][0], bh[2 * p + 1][1],
                       smem_u32(&Bh[cur][bk][bn]));
                ldsm4t(bl[2 * p][0], bl[2 * p][1], bl[2 * p + 1][0], bl[2 * p + 1][1],
                       smem_u32(&Bl[cur][bk][bn]));
            }
#pragma unroll
            for (int mt = 0; mt < 4; mt++)
#pragma unroll
                for (int nt = 0; nt < 4; nt++) {
                    mma_bf16(c[mt][nt], ah[mt], bh[nt][0], bh[nt][1]);
                    mma_bf16(c[mt][nt], ah[mt], bl[nt][0], bl[nt][1]);
                    mma_bf16(c[mt][nt], al[mt], bh[nt][0], bh[nt][1]);
                }
        }
        if (more) {
            const int nxt = 1 - cur;
#pragma unroll
            for (int q = 0; q < 2; q++) {
                uint2 hi, lo; cvt_split(aR[q], hi, lo);
                *reinterpret_cast<uint2*>(&Ah[nxt][fam][fak + q * 4]) = hi;
                *reinterpret_cast<uint2*>(&Al[nxt][fam][fak + q * 4]) = lo;
            }
#pragma unroll
            for (int q = 0; q < 4; q++) {
                uint2 hi, lo; cvt_split(bR[q], hi, lo);
                const int n = (fbn + q * 8) * 4;
                *reinterpret_cast<uint2*>(&Bh[nxt][fbr][n]) = hi;
                *reinterpret_cast<uint2*>(&Bl[nxt][fbr][n]) = lo;
            }
        }
        __syncthreads();
    }

    float* dst = g_ppart[ks];
#pragma unroll
    for (int nt = 0; nt < 4; nt++) {
        const int n = nBase + w * 32 + nt * 8 + (lane & 3) * 2;
#pragma unroll
        for (int mt = 0; mt < 4; mt++) {
            const int m0 = mBase + mt * 16 + (lane >> 2);
            *reinterpret_cast<float2*>(dst + (size_t)m0 * DIN + n) =
                make_float2(c[mt][nt][0], c[mt][nt][1]);
            *reinterpret_cast<float2*>(dst + (size_t)(m0 + 8) * DIN + n) =
                make_float2(c[mt][nt][2], c[mt][nt][3]);
        }
    }
}

// ---------------- K4b: combine partials + bias -> g_pred ------------------
__global__ __launch_bounds__(256) void k_comb(const float* __restrict__ bG) {
    const int idx = blockIdx.x * 256 + threadIdx.x;
    const int S = BB * NOUT * DIN / 4;
    const float4* p = reinterpret_cast<const float4*>(g_ppart);
    float4 a = p[idx], b2 = p[idx + S], c2 = p[idx + 2 * S], d = p[idx + 3 * S];
    const float4 bg = reinterpret_cast<const float4*>(bG)[idx & (DIN / 4 - 1)];
    reinterpret_cast<float4*>(g_pred)[idx] = make_float4(
        a.x + b2.x + c2.x + d.x + bg.x, a.y + b2.y + c2.y + d.y + bg.y,
        a.z + b2.z + c2.z + d.z + bg.z, a.w + b2.w + c2.w + d.w + bg.w);
}

// ---------------- K5 (TENSOR, split-K x2): S partials ----------------------
// Grid (it 0..7, b 0..31, kz 0..1) = 512 CTAs, 128 thr. Tile 128i x 64j, K=512.
__global__ __launch_bounds__(128) void k_sim(const float* __restrict__ x) {
    const int i0 = blockIdx.x * 128;
    const int b = blockIdx.y;
    const int kz = blockIdx.z;
    const int dBase = kz * 512;
    __shared__ __align__(16) uint16_t Ah[2][128][PKP], Al[2][128][PKP];
    __shared__ __align__(16) uint16_t Bh[2][NOUT][PKP], Bl[2][NOUT][PKP];
    const int tid = threadIdx.x, lane = tid & 31, w = tid >> 5;
    const int fbj = tid & 63, fbk = (tid >> 6) * 8;
    const int arow = lane & 15, acol = (lane >> 4) * 8;
    const int brow = ((lane >> 4) & 1) * 8 + (lane & 7), bcol = ((lane >> 3) & 1) * 8;

    const float* Arow = x + ((size_t)b * NI + i0 + tid) * DIN + dBase;
    const float* Brow = g_pred + ((size_t)b * NOUT + fbj) * DIN + dBase;

    float c[2][8][4];
#pragma unroll
    for (int mt = 0; mt < 2; mt++)
#pragma unroll
        for (int nt = 0; nt < 8; nt++)
#pragma unroll
            for (int e = 0; e < 4; e++) c[mt][nt][e] = 0.f;

    float4 aR[4]; float4 bR[2];
#pragma unroll
    for (int q = 0; q < 4; q++)
        aR[q] = *reinterpret_cast<const float4*>(Arow + q * 4);
#pragma unroll
    for (int q = 0; q < 2; q++)
        bR[q] = *reinterpret_cast<const float4*>(Brow + fbk + q * 4);
    {
#pragma unroll
        for (int q = 0; q < 4; q++) {
            uint2 hi, lo; cvt_split(aR[q], hi, lo);
            *reinterpret_cast<uint2*>(&Ah[0][tid][q * 4]) = hi;
            *reinterpret_cast<uint2*>(&Al[0][tid][q * 4]) = lo;
        }
#pragma unroll
        for (int q = 0; q < 2; q++) {
            uint2 hi, lo; cvt_split(bR[q], hi, lo);
            *reinterpret_cast<uint2*>(&Bh[0][fbj][fbk + q * 4]) = hi;
            *reinterpret_cast<uint2*>(&Bl[0][fbj][fbk + q * 4]) = lo;
        }
    }
    __syncthreads();

    const int NSTG = 512 / 16;  // 32
    for (int t = 0; t < NSTG; t++) {
        const int cur = t & 1;
        const bool more = (t + 1 < NSTG);
        if (more) {
            const int d0 = (t + 1) * 16;
#pragma unroll
            for (int q = 0; q < 4; q++)
                aR[q] = *reinterpret_cast<const float4*>(Arow + d0 + q * 4);
#pragma unroll
            for (int q = 0; q < 2; q++)
                bR[q] = *reinterpret_cast<const float4*>(Brow + d0 + fbk + q * 4);
        }
        {
            uint32_t ah[2][4], al[2][4], bh[8][2], bl[8][2];
#pragma unroll
            for (int mt = 0; mt < 2; mt++) {
                const int am = w * 32 + mt * 16 + arow;
                ldsm4(ah[mt][0], ah[mt][1], ah[mt][2], ah[mt][3],
                      smem_u32(&Ah[cur][am][acol]));
                ldsm4(al[mt][0], al[mt][1], al[mt][2], al[mt][3],
                      smem_u32(&Al[cur][am][acol]));
            }
#pragma unroll
            for (int p = 0; p < 4; p++) {
                const int bj = p * 16 + brow;
                ldsm4(bh[2 * p][0], bh[2 * p][1], bh[2 * p + 1][0], bh[2 * p + 1][1],
                      smem_u32(&Bh[cur][bj][bcol]));
                ldsm4(bl[2 * p][0], bl[2 * p][1], bl[2 * p + 1][0], bl[2 * p + 1][1],
                      smem_u32(&Bl[cur][bj][bcol]));
            }
#pragma unroll
            for (int mt = 0; mt < 2; mt++)
#pragma unroll
                for (int nt = 0; nt < 8; nt++) {
                    mma_bf16(c[mt][nt], ah[mt], bh[nt][0], bh[nt][1]);
                    mma_bf16(c[mt][nt], ah[mt], bl[nt][0], bl[nt][1]);
                    mma_bf16(c[mt][nt], al[mt], bh[nt][0], bh[nt][1]);
                }
        }
        if (more) {
            const int nxt = 1 - cur;
#pragma unroll
            for (int q = 0; q < 4; q++) {
                uint2 hi, lo; cvt_split(aR[q], hi, lo);
                *reinterpret_cast<uint2*>(&Ah[nxt][tid][q * 4]) = hi;
                *reinterpret_cast<uint2*>(&Al[nxt][tid][q * 4]) = lo;
            }
#pragma unroll
            for (int q = 0; q < 2; q++) {
                uint2 hi, lo; cvt_split(bR[q], hi, lo);
                *reinterpret_cast<uint2*>(&Bh[nxt][fbj][fbk + q * 4]) = hi;
                *reinterpret_cast<uint2*>(&Bl[nxt][fbj][fbk + q * 4]) = lo;
            }
        }
        __syncthreads();
    }

    // store raw S partials
    float* dst = g_spart[kz];
#pragma unroll
    for (int mt = 0; mt < 2; mt++) {
#pragma unroll
        for (int half = 0; half < 2; half++) {
            const int rg = i0 + w * 32 + mt * 16 + (lane >> 2) + half * 8;
            float* o = dst + ((size_t)b * NI + rg) * NOUT;
#pragma unroll
            for (int nt = 0; nt < 8; nt++) {
                const int jj = nt * 8 + (lane & 3) * 2;
                *reinterpret_cast<float2*>(o + jj) =
                    make_float2(c[mt][nt][half * 2 + 0], c[mt][nt][half * 2 + 1]);
            }
        }
    }
}

// ---------------- K5b: S = sum partials; softmax; phi1 --------------------
// One warp per (b,i) row; 8 warps per block; grid 4096.
__global__ __launch_bounds__(256) void k_soft(const float* __restrict__ bu,
                                              const float* __restrict__ bn) {
    const int row = blockIdx.x * 8 + (threadIdx.x >> 5);  // b*NI + i
    const int lane = threadIdx.x & 31;
    const int b = row >> 10, i = row & (NI - 1);
    const float scale = 0.03125f;
    const float2 s0 = *reinterpret_cast<const float2*>(g_spart[0] + (size_t)row * NOUT + lane * 2);
    const float2 s1 = *reinterpret_cast<const float2*>(g_spart[1] + (size_t)row * NOUT + lane * 2);
    float v0 = (s0.x + s1.x) * scale, v1 = (s0.y + s1.y) * scale;
    float mx = fmaxf(v0, v1);
#pragma unroll
    for (int o = 16; o; o >>= 1) mx = fmaxf(mx, __shfl_xor_sync(0xffffffffu, mx, o));
    float e0 = __expf(v0 - mx), e1 = __expf(v1 - mx);
    float s = e0 + e1;
#pragma unroll
    for (int o = 16; o; o >>= 1) s += __shfl_xor_sync(0xffffffffu, s, o);
    const float inv = 1.f / s;
    const float fa = g_faT[i * BB + b];
    const float2 bu2 = *reinterpret_cast<const float2*>(bu + (size_t)i * NOUT + lane * 2);
    const float2 bn2 = *reinterpret_cast<const float2*>(bn + (size_t)i * NOUT + lane * 2);
    *reinterpret_cast<float2*>(g_phi1 + (size_t)row * NOUT + lane * 2) = make_float2(
        fa * ((bu2.x + bn2.x) * e0 * inv - bn2.x),
        fa * ((bu2.y + bn2.y) * e1 * inv - bn2.y));
}

// ---------------- K6: transpose phi1 [b][i][j] -> phiT [j][i][b] ----------
__global__ __launch_bounds__(256) void k_tr() {
    const int i = blockIdx.x;
    __shared__ float t[32][65];
    const int tid = threadIdx.x;
#pragma unroll
    for (int q = 0; q < 8; q++) {
        int idx = tid + q * 256;
        int bb = idx >> 6, j = idx & 63;
        t[bb][j] = g_phi1[((size_t)bb * NI + i) * NOUT + j];
    }
    __syncthreads();
#pragma unroll
    for (int q = 0; q < 8; q++) {
        int idx = tid + q * 256;
        int j = idx >> 5, bb = idx & 31;
        g_phiT[((size_t)j * NI + i) * BB + bb] = t[bb][j];
    }
}

// ---------------- launch ---------------------------------------------------
extern "C" void kernel_launch(void* const* d_in, const int* in_sizes, int n_in,
                              void* d_out, int out_size) {
    const float* x  = (const float*)d_in[0];
    const float* WA = (const float*)d_in[1];
    const float* bA = (const float*)d_in[2];
    const float* Wm = (const float*)d_in[3];
    const float* WG = (const float*)d_in[4];
    const float* bG = (const float*)d_in[5];
    const float* bu = (const float*)d_in[6];
    const float* bn = (const float*)d_in[7];
    float* out = (float*)d_out;

    k_fa<<<4096, 256>>>(x, WA, bA);
    k_phi0<<<256, 256>>>(bu, bn);
    k_mem<0><<<dim3(8, 64), 128>>>(Wm, nullptr);
    k_predp<<<dim3(8, 32, 4), 128>>>(WG);
    k_comb<<<BB * NOUT * DIN / 1024, 256>>>(bG);
    k_sim<<<dim3(8, 32, 2), 128>>>(x);
    k_soft<<<BB * NI / 8, 256>>>(bu, bn);
    k_tr<<<NI, 256>>>();
    k_mem<1><<<dim3(8, 64), 128>>>(Wm, out);
}

// round 12
// speedup vs baseline: 1.0360x; 1.0360x over previous
#include <cuda_runtime.h>
#include <cuda_bf16.h>
#include <cstdint>

#define BB 32
#define NI 1024
#define DIN 1024
#define NOUT 64
#define DOUT 1024

// ---------------- device scratch ----------------
__device__ float g_faT[NI * BB];              // f_a transposed [i][b]
__device__ float g_xout0[BB * NOUT * DOUT];   // iter-0 output [b][j][h]
__device__ float g_pred[BB * NOUT * DIN];     // pred [b][j][d]
__device__ float g_phi1[BB * NI * NOUT];      // phi iter-1 [b][i][j]
__device__ float g_phiT[NOUT * NI * BB];      // phi transposed [j][i][b]
__device__ float g_ppart[4][BB * NOUT * DIN]; // k_pred split-K partials

// ---------------- mma helpers ----------------
__device__ __forceinline__ uint32_t smem_u32(const void* p) {
    return (uint32_t)__cvta_generic_to_shared(p);
}
__device__ __forceinline__ void ldsm4(uint32_t& r0, uint32_t& r1, uint32_t& r2,
                                      uint32_t& r3, uint32_t a) {
    asm volatile("ldmatrix.sync.aligned.m8n8.x4.shared.b16 {%0,%1,%2,%3}, [%4];"
                 : "=r"(r0), "=r"(r1), "=r"(r2), "=r"(r3) : "r"(a));
}
__device__ __forceinline__ void ldsm4t(uint32_t& r0, uint32_t& r1, uint32_t& r2,
                                       uint32_t& r3, uint32_t a) {
    asm volatile("ldmatrix.sync.aligned.m8n8.x4.trans.shared.b16 {%0,%1,%2,%3}, [%4];"
                 : "=r"(r0), "=r"(r1), "=r"(r2), "=r"(r3) : "r"(a));
}
__device__ __forceinline__ void mma_bf16(float* c, const uint32_t* a,
                                         uint32_t b0, uint32_t b1) {
    asm volatile("mma.sync.aligned.m16n8k16.row.col.f32.bf16.bf16.f32 "
                 "{%0,%1,%2,%3}, {%4,%5,%6,%7}, {%8,%9}, {%0,%1,%2,%3};"
                 : "+f"(c[0]), "+f"(c[1]), "+f"(c[2]), "+f"(c[3])
                 : "r"(a[0]), "r"(a[1]), "r"(a[2]), "r"(a[3]), "r"(b0), "r"(b1));
}
__device__ __forceinline__ uint32_t packbf(__nv_bfloat16 a, __nv_bfloat16 b) {
    return (uint32_t)__bfloat16_as_ushort(a) | ((uint32_t)__bfloat16_as_ushort(b) << 16);
}
__device__ __forceinline__ void cvt_split(float4 v, uint2& hi, uint2& lo) {
    __nv_bfloat16 hx = __float2bfloat16(v.x), hy = __float2bfloat16(v.y);
    __nv_bfloat16 hz = __float2bfloat16(v.z), hw = __float2bfloat16(v.w);
    __nv_bfloat16 lx = __float2bfloat16(v.x - __bfloat162float(hx));
    __nv_bfloat16 ly = __float2bfloat16(v.y - __bfloat162float(hy));
    __nv_bfloat16 lz = __float2bfloat16(v.z - __bfloat162float(hz));
    __nv_bfloat16 lw = __float2bfloat16(v.w - __bfloat162float(hw));
    hi.x = packbf(hx, hy); hi.y = packbf(hz, hw);
    lo.x = packbf(lx, ly); lo.y = packbf(lz, lw);
}

// ---------------- K1: f_a = sigmoid(x . W_A + b_A) -> g_faT[i][b] ---------
__global__ __launch_bounds__(256) void k_fa(const float* __restrict__ x,
                                            const float* __restrict__ WA,
                                            const float* __restrict__ bA) {
    const int row = blockIdx.x * 8 + (threadIdx.x >> 5);
    const int lane = threadIdx.x & 31;
    const float4* xr = reinterpret_cast<const float4*>(x) + (size_t)row * (DIN / 4);
    const float4* w4 = reinterpret_cast<const float4*>(WA);
    float s = 0.f;
#pragma unroll
    for (int q = 0; q < 8; q++) {
        float4 xv = xr[lane + q * 32], wv = w4[lane + q * 32];
        s += xv.x * wv.x + xv.y * wv.y + xv.z * wv.z + xv.w * wv.w;
    }
#pragma unroll
    for (int o = 16; o; o >>= 1) s += __shfl_xor_sync(0xffffffffu, s, o);
    if (lane == 0) {
        const int b = row >> 10, i = row & (NI - 1);
        float tot = s + bA[0];
        g_faT[i * BB + b] = 1.f / (1.f + __expf(-tot));
    }
}

// ---------------- K2: phi0 transposed [j][i][b] ---------------------------
__global__ __launch_bounds__(256) void k_phi0(const float* __restrict__ bu,
                                              const float* __restrict__ bn) {
    const int p = blockIdx.x * 256 + threadIdx.x;
    const int j = p >> 10, i = p & (NI - 1);
    const float cu = bu[i * NOUT + j] * (1.0f / 64.0f) - bn[i * NOUT + j] * (63.0f / 64.0f);
    const float4* fa = reinterpret_cast<const float4*>(&g_faT[i * BB]);
    float4* dst = reinterpret_cast<float4*>(&g_phiT[((size_t)j * NI + i) * BB]);
#pragma unroll
    for (int q = 0; q < 8; q++) {
        float4 v = fa[q];
        dst[q] = make_float4(v.x * cu, v.y * cu, v.z * cu, v.w * cu);
    }
}

// ---------------- K3 (TENSOR, proven): out = phiT . Wm --------------------
// Grid (hb 0..7, j 0..63), 128 thr. Tile 32b x 128h, stage K=32.
#define AMP 40
#define BNP 136
template <int MODE>
__global__ __launch_bounds__(128) void k_mem(const float* __restrict__ Wm,
                                             float* __restrict__ outp) {
    const int j = blockIdx.y, hb = blockIdx.x;
    __shared__ __align__(16) uint16_t Ah[2][32][AMP], Al[2][32][AMP];
    __shared__ __align__(16) uint16_t Bh[2][32][BNP], Bl[2][32][BNP];
    const int tid = threadIdx.x, lane = tid & 31, w = tid >> 5;
    const int fr = tid >> 2, fq = tid & 3;
    const int g = lane >> 3, r = lane & 7;
    const float* WmB = Wm + (size_t)j * DOUT + (size_t)hb * 128;
    const float* Ab = g_phiT + (size_t)j * (NI * BB);

    float c[2][4][4];
#pragma unroll
    for (int mt = 0; mt < 2; mt++)
#pragma unroll
        for (int nt = 0; nt < 4; nt++)
#pragma unroll
            for (int e = 0; e < 4; e++) c[mt][nt][e] = 0.f;

    float4 bR[8], aR[2];
    {
        const float* br = WmB + (size_t)fr * (NOUT * DOUT);
#pragma unroll
        for (int q = 0; q < 8; q++)
            bR[q] = *reinterpret_cast<const float4*>(br + (size_t)(fq + q * 4) * 4);
        const float* ar = Ab + (size_t)fr * BB + fq * 8;
        aR[0] = *reinterpret_cast<const float4*>(ar);
        aR[1] = *reinterpret_cast<const float4*>(ar + 4);
    }
    {
#pragma unroll
        for (int q = 0; q < 8; q++) {
            uint2 hi, lo; cvt_split(bR[q], hi, lo);
            const int n = (fq + q * 4) * 4;
            *reinterpret_cast<uint2*>(&Bh[0][fr][n]) = hi;
            *reinterpret_cast<uint2*>(&Bl[0][fr][n]) = lo;
        }
        uint2 h0, l0, h1, l1;
        cvt_split(aR[0], h0, l0); cvt_split(aR[1], h1, l1);
        const int m = fq * 8;
        *reinterpret_cast<uint4*>(&Ah[0][fr][m]) = make_uint4(h0.x, h0.y, h1.x, h1.y);
        *reinterpret_cast<uint4*>(&Al[0][fr][m]) = make_uint4(l0.x, l0.y, l1.x, l1.y);
    }
    __syncthreads();

    const int NSTG = NI / 32;
    for (int t = 0; t < NSTG; t++) {
        const int cur = t & 1;
        const bool more = (t + 1 < NSTG);
        if (more) {
            const int i0 = (t + 1) * 32;
            const float* br = WmB + (size_t)(i0 + fr) * (NOUT * DOUT);
#pragma unroll
            for (int q = 0; q < 8; q++)
                bR[q] = *reinterpret_cast<const float4*>(br + (size_t)(fq + q * 4) * 4);
            const float* ar = Ab + (size_t)(i0 + fr) * BB + fq * 8;
            aR[0] = *reinterpret_cast<const float4*>(ar);
            aR[1] = *reinterpret_cast<const float4*>(ar + 4);
        }
#pragma unroll
        for (int kk = 0; kk < 32; kk += 16) {
            uint32_t ah[2][4], al[2][4], bh[4][2], bl[4][2];
#pragma unroll
            for (int mt = 0; mt < 2; mt++) {
                const int ak = kk + (g >> 1) * 8 + r, am = mt * 16 + (g & 1) * 8;
                ldsm4t(ah[mt][0], ah[mt][1], ah[mt][2], ah[mt][3],
                       smem_u32(&Ah[cur][ak][am]));
                ldsm4t(al[mt][0], al[mt][1], al[mt][2], al[mt][3],
                       smem_u32(&Al[cur][ak][am]));
            }
#pragma unroll
            for (int p = 0; p < 2; p++) {
                const int bk = kk + (g & 1) * 8 + r;
                const int bn = w * 32 + p * 16 + (g >> 1) * 8;
                ldsm4t(bh[2 * p][0], bh[2 * p][1], bh[2 * p + 1][0], bh[2 * p + 1][1],
                       smem_u32(&Bh[cur][bk][bn]));
                ldsm4t(bl[2 * p][0], bl[2 * p][1], bl[2 * p + 1][0], bl[2 * p + 1][1],
                       smem_u32(&Bl[cur][bk][bn]));
            }
#pragma unroll
            for (int mt = 0; mt < 2; mt++)
#pragma unroll
                for (int nt = 0; nt < 4; nt++) {
                    mma_bf16(c[mt][nt], ah[mt], bh[nt][0], bh[nt][1]);
                    mma_bf16(c[mt][nt], ah[mt], bl[nt][0], bl[nt][1]);
                    mma_bf16(c[mt][nt], al[mt], bh[nt][0], bh[nt][1]);
                }
        }
        if (more) {
            const int nxt = 1 - cur;
#pragma unroll
            for (int q = 0; q < 8; q++) {
                uint2 hi, lo; cvt_split(bR[q], hi, lo);
                const int n = (fq + q * 4) * 4;
                *reinterpret_cast<uint2*>(&Bh[nxt][fr][n]) = hi;
                *reinterpret_cast<uint2*>(&Bl[nxt][fr][n]) = lo;
            }
            uint2 h0, l0, h1, l1;
            cvt_split(aR[0], h0, l0); cvt_split(aR[1], h1, l1);
            const int m = fq * 8;
            *reinterpret_cast<uint4*>(&Ah[nxt][fr][m]) = make_uint4(h0.x, h0.y, h1.x, h1.y);
            *reinterpret_cast<uint4*>(&Al[nxt][fr][m]) = make_uint4(l0.x, l0.y, l1.x, l1.y);
        }
        __syncthreads();
    }

    float* dst = (MODE == 0) ? g_xout0 : outp;
#pragma unroll
    for (int mt = 0; mt < 2; mt++)
#pragma unroll
        for (int nt = 0; nt < 4; nt++) {
            const int m0 = mt * 16 + (lane >> 2);
            const int n = hb * 128 + w * 32 + nt * 8 + (lane & 3) * 2;
            float* o0 = dst + ((size_t)(m0 * NOUT + j)) * DOUT + n;
            *reinterpret_cast<float2*>(o0) = make_float2(c[mt][nt][0], c[mt][nt][1]);
            float* o1 = dst + ((size_t)((m0 + 8) * NOUT + j)) * DOUT + n;
            *reinterpret_cast<float2*>(o1) = make_float2(c[mt][nt][2], c[mt][nt][3]);
        }
}

// ---------------- K4 (TENSOR, split-K): pred partials ---------------------
#define PKP 24
__global__ __launch_bounds__(128) void k_predp(const float* __restrict__ WG) {
    const int nb = blockIdx.x, mb = blockIdx.y, ks = blockIdx.z;
    const int mBase = mb * 64, nBase = nb * 128, kBase = ks * 256;
    __shared__ __align__(16) uint16_t Ah[2][64][PKP], Al[2][64][PKP];
    __shared__ __align__(16) uint16_t Bh[2][16][BNP], Bl[2][16][BNP];
    const int tid = threadIdx.x, lane = tid & 31, w = tid >> 5;
    const int g = lane >> 3, r = lane & 7;
    const int fam = tid & 63, fak = (tid >> 6) * 8;
    const int fbr = tid >> 3, fbn = tid & 7;
    const int arow = lane & 15, acol = (lane >> 4) * 8;

    float c[4][4][4];
#pragma unroll
    for (int mt = 0; mt < 4; mt++)
#pragma unroll
        for (int nt = 0; nt < 4; nt++)
#pragma unroll
            for (int e = 0; e < 4; e++) c[mt][nt][e] = 0.f;

    float4 aR[2], bR[4];
#pragma unroll
    for (int q = 0; q < 2; q++)
        aR[q] = *reinterpret_cast<const float4*>(g_xout0 + (size_t)(mBase + fam) * DOUT + kBase + fak + q * 4);
#pragma unroll
    for (int q = 0; q < 4; q++)
        bR[q] = *reinterpret_cast<const float4*>(WG + (size_t)(kBase + fbr) * DIN + nBase + (size_t)(fbn + q * 8) * 4);
    {
#pragma unroll
        for (int q = 0; q < 2; q++) {
            uint2 hi, lo; cvt_split(aR[q], hi, lo);
            *reinterpret_cast<uint2*>(&Ah[0][fam][fak + q * 4]) = hi;
            *reinterpret_cast<uint2*>(&Al[0][fam][fak + q * 4]) = lo;
        }
#pragma unroll
        for (int q = 0; q < 4; q++) {
            uint2 hi, lo; cvt_split(bR[q], hi, lo);
            const int n = (fbn + q * 8) * 4;
            *reinterpret_cast<uint2*>(&Bh[0][fbr][n]) = hi;
            *reinterpret_cast<uint2*>(&Bl[0][fbr][n]) = lo;
        }
    }
    __syncthreads();

    const int NSTG = 256 / 16;
    for (int t = 0; t < NSTG; t++) {
        const int cur = t & 1;
        const bool more = (t + 1 < NSTG);
        if (more) {
            const int k0 = kBase + (t + 1) * 16;
#pragma unroll
            for (int q = 0; q < 2; q++)
                aR[q] = *reinterpret_cast<const float4*>(g_xout0 + (size_t)(mBase + fam) * DOUT + k0 + fak + q * 4);
#pragma unroll
            for (int q = 0; q < 4; q++)
                bR[q] = *reinterpret_cast<const float4*>(WG + (size_t)(k0 + fbr) * DIN + nBase + (size_t)(fbn + q * 8) * 4);
        }
        {
            uint32_t ah[4][4], al[4][4], bh[4][2], bl[4][2];
#pragma unroll
            for (int mt = 0; mt < 4; mt++) {
                ldsm4(ah[mt][0], ah[mt][1], ah[mt][2], ah[mt][3],
                      smem_u32(&Ah[cur][mt * 16 + arow][acol]));
                ldsm4(al[mt][0], al[mt][1], al[mt][2], al[mt][3],
                      smem_u32(&Al[cur][mt * 16 + arow][acol]));
            }
#pragma unroll
            for (int p = 0; p < 2; p++) {
                const int bk = (g & 1) * 8 + r;
                const int bn = w * 32 + p * 16 + (g >> 1) * 8;
                ldsm4t(bh[2 * p][0], bh[2 * p][1], bh[2 * p + 1][0], bh[2 * p + 1][1],
                       smem_u32(&Bh[cur][bk][bn]));
                ldsm4t(bl[2 * p][0], bl[2 * p][1], bl[2 * p + 1][0], bl[2 * p + 1][1],
                       smem_u32(&Bl[cur][bk][bn]));
            }
#pragma unroll
            for (int mt = 0; mt < 4; mt++)
#pragma unroll
                for (int nt = 0; nt < 4; nt++) {
                    mma_bf16(c[mt][nt], ah[mt], bh[nt][0], bh[nt][1]);
                    mma_bf16(c[mt][nt], ah[mt], bl[nt][0], bl[nt][1]);
                    mma_bf16(c[mt][nt], al[mt], bh[nt][0], bh[nt][1]);
                }
        }
        if (more) {
            const int nxt = 1 - cur;
#pragma unroll
            for (int q = 0; q < 2; q++) {
                uint2 hi, lo; cvt_split(aR[q], hi, lo);
                *reinterpret_cast<uint2*>(&Ah[nxt][fam][fak + q * 4]) = hi;
                *reinterpret_cast<uint2*>(&Al[nxt][fam][fak + q * 4]) = lo;
            }
#pragma unroll
            for (int q = 0; q < 4; q++) {
                uint2 hi, lo; cvt_split(bR[q], hi, lo);
                const int n = (fbn + q * 8) * 4;
                *reinterpret_cast<uint2*>(&Bh[nxt][fbr][n]) = hi;
                *reinterpret_cast<uint2*>(&Bl[nxt][fbr][n]) = lo;
            }
        }
        __syncthreads();
    }

    float* dst = g_ppart[ks];
#pragma unroll
    for (int nt = 0; nt < 4; nt++) {
        const int n = nBase + w * 32 + nt * 8 + (lane & 3) * 2;
#pragma unroll
        for (int mt = 0; mt < 4; mt++) {
            const int m0 = mBase + mt * 16 + (lane >> 2);
            *reinterpret_cast<float2*>(dst + (size_t)m0 * DIN + n) =
                make_float2(c[mt][nt][0], c[mt][nt][1]);
            *reinterpret_cast<float2*>(dst + (size_t)(m0 + 8) * DIN + n) =
                make_float2(c[mt][nt][2], c[mt][nt][3]);
        }
    }
}

// ---------------- K4b: combine partials + bias -> g_pred ------------------
__global__ __launch_bounds__(256) void k_comb(const float* __restrict__ bG) {
    const int idx = blockIdx.x * 256 + threadIdx.x;
    const int S = BB * NOUT * DIN / 4;
    const float4* p = reinterpret_cast<const float4*>(g_ppart);
    float4 a = p[idx], b2 = p[idx + S], c2 = p[idx + 2 * S], d = p[idx + 3 * S];
    const float4 bg = reinterpret_cast<const float4*>(bG)[idx & (DIN / 4 - 1)];
    reinterpret_cast<float4*>(g_pred)[idx] = make_float4(
        a.x + b2.x + c2.x + d.x + bg.x, a.y + b2.y + c2.y + d.y + bg.y,
        a.z + b2.z + c2.z + d.z + bg.z, a.w + b2.w + c2.w + d.w + bg.w);
}

// ---------------- K5 (TENSOR, 256 thr): S -> softmax -> phi1 --------------
// Grid (it 0..7, b 0..31) = 256 CTAs, 256 thr (8 warps). Tile 128i x 64j.
// Warp tile 16i x 64j (mt=1). Stage K=16, same CTA tile as proven round-10.
__global__ __launch_bounds__(256) void k_sim(const float* __restrict__ x,
                                             const float* __restrict__ bu,
                                             const float* __restrict__ bn) {
    const int i0 = blockIdx.x * 128;
    const int b = blockIdx.y;
    __shared__ __align__(16) uint16_t Ah[2][128][PKP], Al[2][128][PKP];
    __shared__ __align__(16) uint16_t Bh[2][NOUT][PKP], Bl[2][NOUT][PKP];
    const int tid = threadIdx.x, lane = tid & 31, w = tid >> 5;
    const int fai = tid & 127, fak = (tid >> 7) * 8;  // A: row, k-half
    const int fbj = tid & 63, fbk = (tid >> 6) * 4;   // B: j row, 4 k
    const int arow = lane & 15, acol = (lane >> 4) * 8;
    const int brow = ((lane >> 4) & 1) * 8 + (lane & 7), bcol = ((lane >> 3) & 1) * 8;

    const float* Arow = x + ((size_t)b * NI + i0 + fai) * DIN;
    const float* Brow = g_pred + ((size_t)b * NOUT + fbj) * DIN;

    float c[8][4];
#pragma unroll
    for (int nt = 0; nt < 8; nt++)
#pragma unroll
        for (int e = 0; e < 4; e++) c[nt][e] = 0.f;

    float4 aR[2]; float4 bR;
#pragma unroll
    for (int q = 0; q < 2; q++)
        aR[q] = *reinterpret_cast<const float4*>(Arow + fak + q * 4);
    bR = *reinterpret_cast<const float4*>(Brow + fbk);
    {
#pragma unroll
        for (int q = 0; q < 2; q++) {
            uint2 hi, lo; cvt_split(aR[q], hi, lo);
            *reinterpret_cast<uint2*>(&Ah[0][fai][fak + q * 4]) = hi;
            *reinterpret_cast<uint2*>(&Al[0][fai][fak + q * 4]) = lo;
        }
        uint2 hi, lo; cvt_split(bR, hi, lo);
        *reinterpret_cast<uint2*>(&Bh[0][fbj][fbk]) = hi;
        *reinterpret_cast<uint2*>(&Bl[0][fbj][fbk]) = lo;
    }
    __syncthreads();

    const int NSTG = DIN / 16;  // 64
    for (int t = 0; t < NSTG; t++) {
        const int cur = t & 1;
        const bool more = (t + 1 < NSTG);
        if (more) {
            const int d0 = (t + 1) * 16;
#pragma unroll
            for (int q = 0; q < 2; q++)
                aR[q] = *reinterpret_cast<const float4*>(Arow + d0 + fak + q * 4);
            bR = *reinterpret_cast<const float4*>(Brow + d0 + fbk);
        }
        {
            uint32_t ah[4], al[4], bh[8][2], bl[8][2];
            const int am = w * 16 + arow;
            ldsm4(ah[0], ah[1], ah[2], ah[3], smem_u32(&Ah[cur][am][acol]));
            ldsm4(al[0], al[1], al[2], al[3], smem_u32(&Al[cur][am][acol]));
#pragma unroll
            for (int p = 0; p < 4; p++) {
                const int bj = p * 16 + brow;
                ldsm4(bh[2 * p][0], bh[2 * p][1], bh[2 * p + 1][0], bh[2 * p + 1][1],
                      smem_u32(&Bh[cur][bj][bcol]));
                ldsm4(bl[2 * p][0], bl[2 * p][1], bl[2 * p + 1][0], bl[2 * p + 1][1],
                      smem_u32(&Bl[cur][bj][bcol]));
            }
#pragma unroll
            for (int nt = 0; nt < 8; nt++) {
                mma_bf16(c[nt], ah, bh[nt][0], bh[nt][1]);
                mma_bf16(c[nt], ah, bl[nt][0], bl[nt][1]);
                mma_bf16(c[nt], al, bh[nt][0], bh[nt][1]);
            }
        }
        if (more) {
            const int nxt = 1 - cur;
#pragma unroll
            for (int q = 0; q < 2; q++) {
                uint2 hi, lo; cvt_split(aR[q], hi, lo);
                *reinterpret_cast<uint2*>(&Ah[nxt][fai][fak + q * 4]) = hi;
                *reinterpret_cast<uint2*>(&Al[nxt][fai][fak + q * 4]) = lo;
            }
            uint2 hi, lo; cvt_split(bR, hi, lo);
            *reinterpret_cast<uint2*>(&Bh[nxt][fbj][fbk]) = hi;
            *reinterpret_cast<uint2*>(&Bl[nxt][fbj][fbk]) = lo;
        }
        __syncthreads();
    }

    // softmax: each row's 64 j live on 4 lanes (xor 1,2), 16 values each
    const float scale = 0.03125f;  // 1024^-0.5
#pragma unroll
    for (int half = 0; half < 2; half++) {
        const int rg = i0 + w * 16 + (lane >> 2) + half * 8;
        float v[16];
#pragma unroll
        for (int nt = 0; nt < 8; nt++) {
            v[nt * 2 + 0] = c[nt][half * 2 + 0] * scale;
            v[nt * 2 + 1] = c[nt][half * 2 + 1] * scale;
        }
        float mx = v[0];
#pragma unroll
        for (int q = 1; q < 16; q++) mx = fmaxf(mx, v[q]);
        mx = fmaxf(mx, __shfl_xor_sync(0xffffffffu, mx, 1));
        mx = fmaxf(mx, __shfl_xor_sync(0xffffffffu, mx, 2));
        float e[16], s = 0.f;
#pragma unroll
        for (int q = 0; q < 16; q++) { e[q] = __expf(v[q] - mx); s += e[q]; }
        s += __shfl_xor_sync(0xffffffffu, s, 1);
        s += __shfl_xor_sync(0xffffffffu, s, 2);
        const float inv = 1.f / s;
        const float fa = g_faT[rg * BB + b];
        float* o = g_phi1 + ((size_t)b * NI + rg) * NOUT;
#pragma unroll
        for (int nt = 0; nt < 8; nt++) {
            const int jj = nt * 8 + (lane & 3) * 2;
            const float2 bu2 = *reinterpret_cast<const float2*>(bu + (size_t)rg * NOUT + jj);
            const float2 bn2 = *reinterpret_cast<const float2*>(bn + (size_t)rg * NOUT + jj);
            *reinterpret_cast<float2*>(o + jj) = make_float2(
                fa * ((bu2.x + bn2.x) * e[nt * 2 + 0] * inv - bn2.x),
                fa * ((bu2.y + bn2.y) * e[nt * 2 + 1] * inv - bn2.y));
        }
    }
}

// ---------------- K6: transpose phi1 [b][i][j] -> phiT [j][i][b] ----------
__global__ __launch_bounds__(256) void k_tr() {
    const int i = blockIdx.x;
    __shared__ float t[32][65];
    const int tid = threadIdx.x;
#pragma unroll
    for (int q = 0; q < 8; q++) {
        int idx = tid + q * 256;
        int bb = idx >> 6, j = idx & 63;
        t[bb][j] = g_phi1[((size_t)bb * NI + i) * NOUT + j];
    }
    __syncthreads();
#pragma unroll
    for (int q = 0; q < 8; q++) {
        int idx = tid + q * 256;
        int j = idx >> 5, bb = idx & 31;
        g_phiT[((size_t)j * NI + i) * BB + bb] = t[bb][j];
    }
}

// ---------------- launch ---------------------------------------------------
extern "C" void kernel_launch(void* const* d_in, const int* in_sizes, int n_in,
                              void* d_out, int out_size) {
    const float* x  = (const float*)d_in[0];
    const float* WA = (const float*)d_in[1];
    const float* bA = (const float*)d_in[2];
    const float* Wm = (const float*)d_in[3];
    const float* WG = (const float*)d_in[4];
    const float* bG = (const float*)d_in[5];
    const float* bu = (const float*)d_in[6];
    const float* bn = (const float*)d_in[7];
    float* out = (float*)d_out;

    k_fa<<<4096, 256>>>(x, WA, bA);
    k_phi0<<<256, 256>>>(bu, bn);
    k_mem<0><<<dim3(8, 64), 128>>>(Wm, nullptr);
    k_predp<<<dim3(8, 32, 4), 128>>>(WG);
    k_comb<<<BB * NOUT * DIN / 1024, 256>>>(bG);
    k_sim<<<dim3(8, 32), 256>>>(x, bu, bn);
    k_tr<<<NI, 256>>>();
    k_mem<1><<<dim3(8, 64), 128>>>(Wm, out);
}

// round 13
// speedup vs baseline: 1.0408x; 1.0046x over previous
#include <cuda_runtime.h>
#include <cuda_bf16.h>
#include <cstdint>

#define BB 32
#define NI 1024
#define DIN 1024
#define NOUT 64
#define DOUT 1024

// ---------------- device scratch ----------------
__device__ float g_faT[NI * BB];              // f_a transposed [i][b]
__device__ float g_xout0[BB * NOUT * DOUT];   // iter-0 output [b][j][h]
__device__ float g_pred[BB * NOUT * DIN];     // pred [b][j][d]
__device__ float g_phi1[BB * NI * NOUT];      // phi iter-1 [b][i][j]
__device__ float g_phiT[NOUT * NI * BB];      // phi transposed [j][i][b]
__device__ float g_ppart[4][BB * NOUT * DIN]; // k_pred split-K partials

// ---------------- mma helpers ----------------
__device__ __forceinline__ uint32_t smem_u32(const void* p) {
    return (uint32_t)__cvta_generic_to_shared(p);
}
__device__ __forceinline__ void ldsm4(uint32_t& r0, uint32_t& r1, uint32_t& r2,
                                      uint32_t& r3, uint32_t a) {
    asm volatile("ldmatrix.sync.aligned.m8n8.x4.shared.b16 {%0,%1,%2,%3}, [%4];"
                 : "=r"(r0), "=r"(r1), "=r"(r2), "=r"(r3) : "r"(a));
}
__device__ __forceinline__ void ldsm4t(uint32_t& r0, uint32_t& r1, uint32_t& r2,
                                       uint32_t& r3, uint32_t a) {
    asm volatile("ldmatrix.sync.aligned.m8n8.x4.trans.shared.b16 {%0,%1,%2,%3}, [%4];"
                 : "=r"(r0), "=r"(r1), "=r"(r2), "=r"(r3) : "r"(a));
}
__device__ __forceinline__ void mma_bf16(float* c, const uint32_t* a,
                                         uint32_t b0, uint32_t b1) {
    asm volatile("mma.sync.aligned.m16n8k16.row.col.f32.bf16.bf16.f32 "
                 "{%0,%1,%2,%3}, {%4,%5,%6,%7}, {%8,%9}, {%0,%1,%2,%3};"
                 : "+f"(c[0]), "+f"(c[1]), "+f"(c[2]), "+f"(c[3])
                 : "r"(a[0]), "r"(a[1]), "r"(a[2]), "r"(a[3]), "r"(b0), "r"(b1));
}
__device__ __forceinline__ uint32_t packbf(__nv_bfloat16 a, __nv_bfloat16 b) {
    return (uint32_t)__bfloat16_as_ushort(a) | ((uint32_t)__bfloat16_as_ushort(b) << 16);
}
__device__ __forceinline__ void cvt_split(float4 v, uint2& hi, uint2& lo) {
    __nv_bfloat16 hx = __float2bfloat16(v.x), hy = __float2bfloat16(v.y);
    __nv_bfloat16 hz = __float2bfloat16(v.z), hw = __float2bfloat16(v.w);
    __nv_bfloat16 lx = __float2bfloat16(v.x - __bfloat162float(hx));
    __nv_bfloat16 ly = __float2bfloat16(v.y - __bfloat162float(hy));
    __nv_bfloat16 lz = __float2bfloat16(v.z - __bfloat162float(hz));
    __nv_bfloat16 lw = __float2bfloat16(v.w - __bfloat162float(hw));
    hi.x = packbf(hx, hy); hi.y = packbf(hz, hw);
    lo.x = packbf(lx, ly); lo.y = packbf(lz, lw);
}

// ---------------- K1: f_a = sigmoid(x . W_A + b_A) -> g_faT[i][b] ---------
__global__ __launch_bounds__(256) void k_fa(const float* __restrict__ x,
                                            const float* __restrict__ WA,
                                            const float* __restrict__ bA) {
    const int row = blockIdx.x * 8 + (threadIdx.x >> 5);
    const int lane = threadIdx.x & 31;
    const float4* xr = reinterpret_cast<const float4*>(x) + (size_t)row * (DIN / 4);
    const float4* w4 = reinterpret_cast<const float4*>(WA);
    float s = 0.f;
#pragma unroll
    for (int q = 0; q < 8; q++) {
        float4 xv = xr[lane + q * 32], wv = w4[lane + q * 32];
        s += xv.x * wv.x + xv.y * wv.y + xv.z * wv.z + xv.w * wv.w;
    }
#pragma unroll
    for (int o = 16; o; o >>= 1) s += __shfl_xor_sync(0xffffffffu, s, o);
    if (lane == 0) {
        const int b = row >> 10, i = row & (NI - 1);
        float tot = s + bA[0];
        g_faT[i * BB + b] = 1.f / (1.f + __expf(-tot));
    }
}

// ---------------- K2: phi0 transposed [j][i][b] ---------------------------
__global__ __launch_bounds__(256) void k_phi0(const float* __restrict__ bu,
                                              const float* __restrict__ bn) {
    const int p = blockIdx.x * 256 + threadIdx.x;
    const int j = p >> 10, i = p & (NI - 1);
    const float cu = bu[i * NOUT + j] * (1.0f / 64.0f) - bn[i * NOUT + j] * (63.0f / 64.0f);
    const float4* fa = reinterpret_cast<const float4*>(&g_faT[i * BB]);
    float4* dst = reinterpret_cast<float4*>(&g_phiT[((size_t)j * NI + i) * BB]);
#pragma unroll
    for (int q = 0; q < 8; q++) {
        float4 v = fa[q];
        dst[q] = make_float4(v.x * cu, v.y * cu, v.z * cu, v.w * cu);
    }
}

// ---------------- K3 (TENSOR, proven): out = phiT . Wm --------------------
#define AMP 40
#define BNP 136
template <int MODE>
__global__ __launch_bounds__(128) void k_mem(const float* __restrict__ Wm,
                                             float* __restrict__ outp) {
    const int j = blockIdx.y, hb = blockIdx.x;
    __shared__ __align__(16) uint16_t Ah[2][32][AMP], Al[2][32][AMP];
    __shared__ __align__(16) uint16_t Bh[2][32][BNP], Bl[2][32][BNP];
    const int tid = threadIdx.x, lane = tid & 31, w = tid >> 5;
    const int fr = tid >> 2, fq = tid & 3;
    const int g = lane >> 3, r = lane & 7;
    const float* WmB = Wm + (size_t)j * DOUT + (size_t)hb * 128;
    const float* Ab = g_phiT + (size_t)j * (NI * BB);

    float c[2][4][4];
#pragma unroll
    for (int mt = 0; mt < 2; mt++)
#pragma unroll
        for (int nt = 0; nt < 4; nt++)
#pragma unroll
            for (int e = 0; e < 4; e++) c[mt][nt][e] = 0.f;

    float4 bR[8], aR[2];
    {
        const float* br = WmB + (size_t)fr * (NOUT * DOUT);
#pragma unroll
        for (int q = 0; q < 8; q++)
            bR[q] = *reinterpret_cast<const float4*>(br + (size_t)(fq + q * 4) * 4);
        const float* ar = Ab + (size_t)fr * BB + fq * 8;
        aR[0] = *reinterpret_cast<const float4*>(ar);
        aR[1] = *reinterpret_cast<const float4*>(ar + 4);
    }
    {
#pragma unroll
        for (int q = 0; q < 8; q++) {
            uint2 hi, lo; cvt_split(bR[q], hi, lo);
            const int n = (fq + q * 4) * 4;
            *reinterpret_cast<uint2*>(&Bh[0][fr][n]) = hi;
            *reinterpret_cast<uint2*>(&Bl[0][fr][n]) = lo;
        }
        uint2 h0, l0, h1, l1;
        cvt_split(aR[0], h0, l0); cvt_split(aR[1], h1, l1);
        const int m = fq * 8;
        *reinterpret_cast<uint4*>(&Ah[0][fr][m]) = make_uint4(h0.x, h0.y, h1.x, h1.y);
        *reinterpret_cast<uint4*>(&Al[0][fr][m]) = make_uint4(l0.x, l0.y, l1.x, l1.y);
    }
    __syncthreads();

    const int NSTG = NI / 32;
    for (int t = 0; t < NSTG; t++) {
        const int cur = t & 1;
        const bool more = (t + 1 < NSTG);
        if (more) {
            const int i0 = (t + 1) * 32;
            const float* br = WmB + (size_t)(i0 + fr) * (NOUT * DOUT);
#pragma unroll
            for (int q = 0; q < 8; q++)
                bR[q] = *reinterpret_cast<const float4*>(br + (size_t)(fq + q * 4) * 4);
            const float* ar = Ab + (size_t)(i0 + fr) * BB + fq * 8;
            aR[0] = *reinterpret_cast<const float4*>(ar);
            aR[1] = *reinterpret_cast<const float4*>(ar + 4);
        }
#pragma unroll
        for (int kk = 0; kk < 32; kk += 16) {
            uint32_t ah[2][4], al[2][4], bh[4][2], bl[4][2];
#pragma unroll
            for (int mt = 0; mt < 2; mt++) {
                const int ak = kk + (g >> 1) * 8 + r, am = mt * 16 + (g & 1) * 8;
                ldsm4t(ah[mt][0], ah[mt][1], ah[mt][2], ah[mt][3],
                       smem_u32(&Ah[cur][ak][am]));
                ldsm4t(al[mt][0], al[mt][1], al[mt][2], al[mt][3],
                       smem_u32(&Al[cur][ak][am]));
            }
#pragma unroll
            for (int p = 0; p < 2; p++) {
                const int bk = kk + (g & 1) * 8 + r;
                const int bn = w * 32 + p * 16 + (g >> 1) * 8;
                ldsm4t(bh[2 * p][0], bh[2 * p][1], bh[2 * p + 1][0], bh[2 * p + 1][1],
                       smem_u32(&Bh[cur][bk][bn]));
                ldsm4t(bl[2 * p][0], bl[2 * p][1], bl[2 * p + 1][0], bl[2 * p + 1][1],
                       smem_u32(&Bl[cur][bk][bn]));
            }
#pragma unroll
            for (int mt = 0; mt < 2; mt++)
#pragma unroll
                for (int nt = 0; nt < 4; nt++) {
                    mma_bf16(c[mt][nt], ah[mt], bh[nt][0], bh[nt][1]);
                    mma_bf16(c[mt][nt], ah[mt], bl[nt][0], bl[nt][1]);
                    mma_bf16(c[mt][nt], al[mt], bh[nt][0], bh[nt][1]);
                }
        }
        if (more) {
            const int nxt = 1 - cur;
#pragma unroll
            for (int q = 0; q < 8; q++) {
                uint2 hi, lo; cvt_split(bR[q], hi, lo);
                const int n = (fq + q * 4) * 4;
                *reinterpret_cast<uint2*>(&Bh[nxt][fr][n]) = hi;
                *reinterpret_cast<uint2*>(&Bl[nxt][fr][n]) = lo;
            }
            uint2 h0, l0, h1, l1;
            cvt_split(aR[0], h0, l0); cvt_split(aR[1], h1, l1);
            const int m = fq * 8;
            *reinterpret_cast<uint4*>(&Ah[nxt][fr][m]) = make_uint4(h0.x, h0.y, h1.x, h1.y);
            *reinterpret_cast<uint4*>(&Al[nxt][fr][m]) = make_uint4(l0.x, l0.y, l1.x, l1.y);
        }
        __syncthreads();
    }

    float* dst = (MODE == 0) ? g_xout0 : outp;
#pragma unroll
    for (int mt = 0; mt < 2; mt++)
#pragma unroll
        for (int nt = 0; nt < 4; nt++) {
            const int m0 = mt * 16 + (lane >> 2);
            const int n = hb * 128 + w * 32 + nt * 8 + (lane & 3) * 2;
            float* o0 = dst + ((size_t)(m0 * NOUT + j)) * DOUT + n;
            *reinterpret_cast<float2*>(o0) = make_float2(c[mt][nt][0], c[mt][nt][1]);
            float* o1 = dst + ((size_t)((m0 + 8) * NOUT + j)) * DOUT + n;
            *reinterpret_cast<float2*>(o1) = make_float2(c[mt][nt][2], c[mt][nt][3]);
        }
}

// ---------------- K4 (TENSOR, split-K): pred partials ---------------------
#define PKP 24
__global__ __launch_bounds__(128) void k_predp(const float* __restrict__ WG) {
    const int nb = blockIdx.x, mb = blockIdx.y, ks = blockIdx.z;
    const int mBase = mb * 64, nBase = nb * 128, kBase = ks * 256;
    __shared__ __align__(16) uint16_t Ah[2][64][PKP], Al[2][64][PKP];
    __shared__ __align__(16) uint16_t Bh[2][16][BNP], Bl[2][16][BNP];
    const int tid = threadIdx.x, lane = tid & 31, w = tid >> 5;
    const int g = lane >> 3, r = lane & 7;
    const int fam = tid & 63, fak = (tid >> 6) * 8;
    const int fbr = tid >> 3, fbn = tid & 7;
    const int arow = lane & 15, acol = (lane >> 4) * 8;

    float c[4][4][4];
#pragma unroll
    for (int mt = 0; mt < 4; mt++)
#pragma unroll
        for (int nt = 0; nt < 4; nt++)
#pragma unroll
            for (int e = 0; e < 4; e++) c[mt][nt][e] = 0.f;

    float4 aR[2], bR[4];
#pragma unroll
    for (int q = 0; q < 2; q++)
        aR[q] = *reinterpret_cast<const float4*>(g_xout0 + (size_t)(mBase + fam) * DOUT + kBase + fak + q * 4);
#pragma unroll
    for (int q = 0; q < 4; q++)
        bR[q] = *reinterpret_cast<const float4*>(WG + (size_t)(kBase + fbr) * DIN + nBase + (size_t)(fbn + q * 8) * 4);
    {
#pragma unroll
        for (int q = 0; q < 2; q++) {
            uint2 hi, lo; cvt_split(aR[q], hi, lo);
            *reinterpret_cast<uint2*>(&Ah[0][fam][fak + q * 4]) = hi;
            *reinterpret_cast<uint2*>(&Al[0][fam][fak + q * 4]) = lo;
        }
#pragma unroll
        for (int q = 0; q < 4; q++) {
            uint2 hi, lo; cvt_split(bR[q], hi, lo);
            const int n = (fbn + q * 8) * 4;
            *reinterpret_cast<uint2*>(&Bh[0][fbr][n]) = hi;
            *reinterpret_cast<uint2*>(&Bl[0][fbr][n]) = lo;
        }
    }
    __syncthreads();

    const int NSTG = 256 / 16;
    for (int t = 0; t < NSTG; t++) {
        const int cur = t & 1;
        const bool more = (t + 1 < NSTG);
        if (more) {
            const int k0 = kBase + (t + 1) * 16;
#pragma unroll
            for (int q = 0; q < 2; q++)
                aR[q] = *reinterpret_cast<const float4*>(g_xout0 + (size_t)(mBase + fam) * DOUT + k0 + fak + q * 4);
#pragma unroll
            for (int q = 0; q < 4; q++)
                bR[q] = *reinterpret_cast<const float4*>(WG + (size_t)(k0 + fbr) * DIN + nBase + (size_t)(fbn + q * 8) * 4);
        }
        {
            uint32_t ah[4][4], al[4][4], bh[4][2], bl[4][2];
#pragma unroll
            for (int mt = 0; mt < 4; mt++) {
                ldsm4(ah[mt][0], ah[mt][1], ah[mt][2], ah[mt][3],
                      smem_u32(&Ah[cur][mt * 16 + arow][acol]));
                ldsm4(al[mt][0], al[mt][1], al[mt][2], al[mt][3],
                      smem_u32(&Al[cur][mt * 16 + arow][acol]));
            }
#pragma unroll
            for (int p = 0; p < 2; p++) {
                const int bk = (g & 1) * 8 + r;
                const int bn = w * 32 + p * 16 + (g >> 1) * 8;
                ldsm4t(bh[2 * p][0], bh[2 * p][1], bh[2 * p + 1][0], bh[2 * p + 1][1],
                       smem_u32(&Bh[cur][bk][bn]));
                ldsm4t(bl[2 * p][0], bl[2 * p][1], bl[2 * p + 1][0], bl[2 * p + 1][1],
                       smem_u32(&Bl[cur][bk][bn]));
            }
#pragma unroll
            for (int mt = 0; mt < 4; mt++)
#pragma unroll
                for (int nt = 0; nt < 4; nt++) {
                    mma_bf16(c[mt][nt], ah[mt], bh[nt][0], bh[nt][1]);
                    mma_bf16(c[mt][nt], ah[mt], bl[nt][0], bl[nt][1]);
                    mma_bf16(c[mt][nt], al[mt], bh[nt][0], bh[nt][1]);
                }
        }
        if (more) {
            const int nxt = 1 - cur;
#pragma unroll
            for (int q = 0; q < 2; q++) {
                uint2 hi, lo; cvt_split(aR[q], hi, lo);
                *reinterpret_cast<uint2*>(&Ah[nxt][fam][fak + q * 4]) = hi;
                *reinterpret_cast<uint2*>(&Al[nxt][fam][fak + q * 4]) = lo;
            }
#pragma unroll
            for (int q = 0; q < 4; q++) {
                uint2 hi, lo; cvt_split(bR[q], hi, lo);
                const int n = (fbn + q * 8) * 4;
                *reinterpret_cast<uint2*>(&Bh[nxt][fbr][n]) = hi;
                *reinterpret_cast<uint2*>(&Bl[nxt][fbr][n]) = lo;
            }
        }
        __syncthreads();
    }

    float* dst = g_ppart[ks];
#pragma unroll
    for (int nt = 0; nt < 4; nt++) {
        const int n = nBase + w * 32 + nt * 8 + (lane & 3) * 2;
#pragma unroll
        for (int mt = 0; mt < 4; mt++) {
            const int m0 = mBase + mt * 16 + (lane >> 2);
            *reinterpret_cast<float2*>(dst + (size_t)m0 * DIN + n) =
                make_float2(c[mt][nt][0], c[mt][nt][1]);
            *reinterpret_cast<float2*>(dst + (size_t)(m0 + 8) * DIN + n) =
                make_float2(c[mt][nt][2], c[mt][nt][3]);
        }
    }
}

// ---------------- K4b: combine partials + bias -> g_pred ------------------
__global__ __launch_bounds__(256) void k_comb(const float* __restrict__ bG) {
    const int idx = blockIdx.x * 256 + threadIdx.x;
    const int S = BB * NOUT * DIN / 4;
    const float4* p = reinterpret_cast<const float4*>(g_ppart);
    float4 a = p[idx], b2 = p[idx + S], c2 = p[idx + 2 * S], d = p[idx + 3 * S];
    const float4 bg = reinterpret_cast<const float4*>(bG)[idx & (DIN / 4 - 1)];
    reinterpret_cast<float4*>(g_pred)[idx] = make_float4(
        a.x + b2.x + c2.x + d.x + bg.x, a.y + b2.y + c2.y + d.y + bg.y,
        a.z + b2.z + c2.z + d.z + bg.z, a.w + b2.w + c2.w + d.w + bg.w);
}

// ---------------- K5 (TENSOR, 8 warps, 4x2 split): S -> softmax -> phi1 ---
// Grid (it 0..7, b 0..31) = 256 CTAs, 256 thr. CTA tile 128i x 64j.
// Warp tile 32i x 32j: iw = w&3 (i-group), jw = w>>2 (j-half).
// Per warp-k16: 8 ldsm / 24 MMAs. Cross-warp softmax via (m,s) merge in smem.
__global__ __launch_bounds__(256) void k_sim(const float* __restrict__ x,
                                             const float* __restrict__ bu,
                                             const float* __restrict__ bn) {
    const int i0 = blockIdx.x * 128;
    const int b = blockIdx.y;
    __shared__ __align__(16) uint16_t Ah[2][128][PKP], Al[2][128][PKP];
    __shared__ __align__(16) uint16_t Bh[2][NOUT][PKP], Bl[2][NOUT][PKP];
    __shared__ float red_m[128][2], red_s[128][2];
    const int tid = threadIdx.x, lane = tid & 31, w = tid >> 5;
    const int iw = w & 3, jw = w >> 2;
    const int fai = tid & 127, fak = (tid >> 7) * 8;
    const int fbj = tid & 63, fbk = (tid >> 6) * 4;
    const int arow = lane & 15, acol = (lane >> 4) * 8;
    const int brow = ((lane >> 4) & 1) * 8 + (lane & 7), bcol = ((lane >> 3) & 1) * 8;

    const float* Arow = x + ((size_t)b * NI + i0 + fai) * DIN;
    const float* Brow = g_pred + ((size_t)b * NOUT + fbj) * DIN;

    float c[2][4][4];  // [mt 16i][nt 8j of 32] [4]
#pragma unroll
    for (int mt = 0; mt < 2; mt++)
#pragma unroll
        for (int nt = 0; nt < 4; nt++)
#pragma unroll
            for (int e = 0; e < 4; e++) c[mt][nt][e] = 0.f;

    float4 aR[2]; float4 bR;
#pragma unroll
    for (int q = 0; q < 2; q++)
        aR[q] = *reinterpret_cast<const float4*>(Arow + fak + q * 4);
    bR = *reinterpret_cast<const float4*>(Brow + fbk);
    {
#pragma unroll
        for (int q = 0; q < 2; q++) {
            uint2 hi, lo; cvt_split(aR[q], hi, lo);
            *reinterpret_cast<uint2*>(&Ah[0][fai][fak + q * 4]) = hi;
            *reinterpret_cast<uint2*>(&Al[0][fai][fak + q * 4]) = lo;
        }
        uint2 hi, lo; cvt_split(bR, hi, lo);
        *reinterpret_cast<uint2*>(&Bh[0][fbj][fbk]) = hi;
        *reinterpret_cast<uint2*>(&Bl[0][fbj][fbk]) = lo;
    }
    __syncthreads();

    const int NSTG = DIN / 16;  // 64
    for (int t = 0; t < NSTG; t++) {
        const int cur = t & 1;
        const bool more = (t + 1 < NSTG);
        if (more) {
            const int d0 = (t + 1) * 16;
#pragma unroll
            for (int q = 0; q < 2; q++)
                aR[q] = *reinterpret_cast<const float4*>(Arow + d0 + fak + q * 4);
            bR = *reinterpret_cast<const float4*>(Brow + d0 + fbk);
        }
        {
            uint32_t ah[2][4], al[2][4], bh[4][2], bl[4][2];
#pragma unroll
            for (int mt = 0; mt < 2; mt++) {
                const int am = iw * 32 + mt * 16 + arow;
                ldsm4(ah[mt][0], ah[mt][1], ah[mt][2], ah[mt][3],
                      smem_u32(&Ah[cur][am][acol]));
                ldsm4(al[mt][0], al[mt][1], al[mt][2], al[mt][3],
                      smem_u32(&Al[cur][am][acol]));
            }
#pragma unroll
            for (int p = 0; p < 2; p++) {
                const int bj = jw * 32 + p * 16 + brow;
                ldsm4(bh[2 * p][0], bh[2 * p][1], bh[2 * p + 1][0], bh[2 * p + 1][1],
                      smem_u32(&Bh[cur][bj][bcol]));
                ldsm4(bl[2 * p][0], bl[2 * p][1], bl[2 * p + 1][0], bl[2 * p + 1][1],
                      smem_u32(&Bl[cur][bj][bcol]));
            }
#pragma unroll
            for (int mt = 0; mt < 2; mt++)
#pragma unroll
                for (int nt = 0; nt < 4; nt++) {
                    mma_bf16(c[mt][nt], ah[mt], bh[nt][0], bh[nt][1]);
                    mma_bf16(c[mt][nt], ah[mt], bl[nt][0], bl[nt][1]);
                    mma_bf16(c[mt][nt], al[mt], bh[nt][0], bh[nt][1]);
                }
        }
        if (more) {
            const int nxt = 1 - cur;
#pragma unroll
            for (int q = 0; q < 2; q++) {
                uint2 hi, lo; cvt_split(aR[q], hi, lo);
                *reinterpret_cast<uint2*>(&Ah[nxt][fai][fak + q * 4]) = hi;
                *reinterpret_cast<uint2*>(&Al[nxt][fai][fak + q * 4]) = lo;
            }
            uint2 hi, lo; cvt_split(bR, hi, lo);
            *reinterpret_cast<uint2*>(&Bh[nxt][fbj][fbk]) = hi;
            *reinterpret_cast<uint2*>(&Bl[nxt][fbj][fbk]) = lo;
        }
        __syncthreads();
    }

    // phase 1: per-warp partial softmax over its 32-j half (xor 1,2)
    const float scale = 0.03125f;  // 1024^-0.5
    float mh[2][2];
#pragma unroll
    for (int mt = 0; mt < 2; mt++) {
#pragma unroll
        for (int half = 0; half < 2; half++) {
            float v[8];
#pragma unroll
            for (int nt = 0; nt < 4; nt++) {
                v[nt * 2 + 0] = c[mt][nt][half * 2 + 0] * scale;
                v[nt * 2 + 1] = c[mt][nt][half * 2 + 1] * scale;
            }
            float m = v[0];
#pragma unroll
            for (int q = 1; q < 8; q++) m = fmaxf(m, v[q]);
            m = fmaxf(m, __shfl_xor_sync(0xffffffffu, m, 1));
            m = fmaxf(m, __shfl_xor_sync(0xffffffffu, m, 2));
            float s = 0.f;
#pragma unroll
            for (int q = 0; q < 8; q++) {
                float e = __expf(v[q] - m);
                c[mt][q >> 1][half * 2 + (q & 1)] = e;  // stash exp in-place
                s += e;
            }
            s += __shfl_xor_sync(0xffffffffu, s, 1);
            s += __shfl_xor_sync(0xffffffffu, s, 2);
            mh[mt][half] = m;
            const int rloc = iw * 32 + mt * 16 + (lane >> 2) + half * 8;
            if ((lane & 3) == 0) { red_m[rloc][jw] = m; red_s[rloc][jw] = s; }
        }
    }
    __syncthreads();

    // phase 2: merge halves, write phi
#pragma unroll
    for (int mt = 0; mt < 2; mt++) {
#pragma unroll
        for (int half = 0; half < 2; half++) {
            const int rloc = iw * 32 + mt * 16 + (lane >> 2) + half * 8;
            const int rg = i0 + rloc;
            const float m0 = red_m[rloc][0], m1 = red_m[rloc][1];
            const float s0 = red_s[rloc][0], s1 = red_s[rloc][1];
            const float M = fmaxf(m0, m1);
            const float S = s0 * __expf(m0 - M) + s1 * __expf(m1 - M);
            const float fac = __expf(mh[mt][half] - M) / S;
            const float fa = g_faT[rg * BB + b];
            float* o = g_phi1 + ((size_t)b * NI + rg) * NOUT;
#pragma unroll
            for (int nt = 0; nt < 4; nt++) {
                const int jj = jw * 32 + nt * 8 + (lane & 3) * 2;
                const float2 bu2 = *reinterpret_cast<const float2*>(bu + (size_t)rg * NOUT + jj);
                const float2 bn2 = *reinterpret_cast<const float2*>(bn + (size_t)rg * NOUT + jj);
                const float R0 = c[mt][nt][half * 2 + 0] * fac;
                const float R1 = c[mt][nt][half * 2 + 1] * fac;
                *reinterpret_cast<float2*>(o + jj) = make_float2(
                    fa * ((bu2.x + bn2.x) * R0 - bn2.x),
                    fa * ((bu2.y + bn2.y) * R1 - bn2.y));
            }
        }
    }
}

// ---------------- K6: transpose phi1 [b][i][j] -> phiT [j][i][b] ----------
__global__ __launch_bounds__(256) void k_tr() {
    const int i = blockIdx.x;
    __shared__ float t[32][65];
    const int tid = threadIdx.x;
#pragma unroll
    for (int q = 0; q < 8; q++) {
        int idx = tid + q * 256;
        int bb = idx >> 6, j = idx & 63;
        t[bb][j] = g_phi1[((size_t)bb * NI + i) * NOUT + j];
    }
    __syncthreads();
#pragma unroll
    for (int q = 0; q < 8; q++) {
        int idx = tid + q * 256;
        int j = idx >> 5, bb = idx & 31;
        g_phiT[((size_t)j * NI + i) * BB + bb] = t[bb][j];
    }
}

// ---------------- launch ---------------------------------------------------
extern "C" void kernel_launch(void* const* d_in, const int* in_sizes, int n_in,
                              void* d_out, int out_size) {
    const float* x  = (const float*)d_in[0];
    const float* WA = (const float*)d_in[1];
    const float* bA = (const float*)d_in[2];
    const float* Wm = (const float*)d_in[3];
    const float* WG = (const float*)d_in[4];
    const float* bG = (const float*)d_in[5];
    const float* bu = (const float*)d_in[6];
    const float* bn = (const float*)d_in[7];
    float* out = (float*)d_out;

    k_fa<<<4096, 256>>>(x, WA, bA);
    k_phi0<<<256, 256>>>(bu, bn);
    k_mem<0><<<dim3(8, 64), 128>>>(Wm, nullptr);
    k_predp<<<dim3(8, 32, 4), 128>>>(WG);
    k_comb<<<BB * NOUT * DIN / 1024, 256>>>(bG);
    k_sim<<<dim3(8, 32), 256>>>(x, bu, bn);
    k_tr<<<NI, 256>>>();
    k_mem<1><<<dim3(8, 64), 128>>>(Wm, out);
}

// round 14
// speedup vs baseline: 1.0429x; 1.0020x over previous
#include <cuda_runtime.h>
#include <cuda_bf16.h>
#include <cstdint>

#define BB 32
#define NI 1024
#define DIN 1024
#define NOUT 64
#define DOUT 1024

// ---------------- device scratch ----------------
__device__ float g_faT[NI * BB];              // f_a transposed [i][b]
__device__ float g_xout0[BB * NOUT * DOUT];   // iter-0 output [b][j][h]
__device__ float g_pred[BB * NOUT * DIN];     // pred [b][j][d]
__device__ float g_phi1[BB * NI * NOUT];      // phi iter-1 [b][i][j]
__device__ float g_phiT[NOUT * NI * BB];      // phi transposed [j][i][b]
__device__ float g_ppart[4][BB * NOUT * DIN]; // k_pred split-K partials

// ---------------- mma helpers ----------------
__device__ __forceinline__ uint32_t smem_u32(const void* p) {
    return (uint32_t)__cvta_generic_to_shared(p);
}
__device__ __forceinline__ void ldsm4(uint32_t& r0, uint32_t& r1, uint32_t& r2,
                                      uint32_t& r3, uint32_t a) {
    asm volatile("ldmatrix.sync.aligned.m8n8.x4.shared.b16 {%0,%1,%2,%3}, [%4];"
                 : "=r"(r0), "=r"(r1), "=r"(r2), "=r"(r3) : "r"(a));
}
__device__ __forceinline__ void ldsm4t(uint32_t& r0, uint32_t& r1, uint32_t& r2,
                                       uint32_t& r3, uint32_t a) {
    asm volatile("ldmatrix.sync.aligned.m8n8.x4.trans.shared.b16 {%0,%1,%2,%3}, [%4];"
                 : "=r"(r0), "=r"(r1), "=r"(r2), "=r"(r3) : "r"(a));
}
__device__ __forceinline__ void mma_bf16(float* c, const uint32_t* a,
                                         uint32_t b0, uint32_t b1) {
    asm volatile("mma.sync.aligned.m16n8k16.row.col.f32.bf16.bf16.f32 "
                 "{%0,%1,%2,%3}, {%4,%5,%6,%7}, {%8,%9}, {%0,%1,%2,%3};"
                 : "+f"(c[0]), "+f"(c[1]), "+f"(c[2]), "+f"(c[3])
                 : "r"(a[0]), "r"(a[1]), "r"(a[2]), "r"(a[3]), "r"(b0), "r"(b1));
}
__device__ __forceinline__ uint32_t packbf(__nv_bfloat16 a, __nv_bfloat16 b) {
    return (uint32_t)__bfloat16_as_ushort(a) | ((uint32_t)__bfloat16_as_ushort(b) << 16);
}
__device__ __forceinline__ void cvt_split(float4 v, uint2& hi, uint2& lo) {
    __nv_bfloat16 hx = __float2bfloat16(v.x), hy = __float2bfloat16(v.y);
    __nv_bfloat16 hz = __float2bfloat16(v.z), hw = __float2bfloat16(v.w);
    __nv_bfloat16 lx = __float2bfloat16(v.x - __bfloat162float(hx));
    __nv_bfloat16 ly = __float2bfloat16(v.y - __bfloat162float(hy));
    __nv_bfloat16 lz = __float2bfloat16(v.z - __bfloat162float(hz));
    __nv_bfloat16 lw = __float2bfloat16(v.w - __bfloat162float(hw));
    hi.x = packbf(hx, hy); hi.y = packbf(hz, hw);
    lo.x = packbf(lx, ly); lo.y = packbf(lz, lw);
}

// ---------------- K1: f_a = sigmoid(x . W_A + b_A) -> g_faT[i][b] ---------
__global__ __launch_bounds__(256) void k_fa(const float* __restrict__ x,
                                            const float* __restrict__ WA,
                                            const float* __restrict__ bA) {
    const int row = blockIdx.x * 8 + (threadIdx.x >> 5);
    const int lane = threadIdx.x & 31;
    const float4* xr = reinterpret_cast<const float4*>(x) + (size_t)row * (DIN / 4);
    const float4* w4 = reinterpret_cast<const float4*>(WA);
    float s = 0.f;
#pragma unroll
    for (int q = 0; q < 8; q++) {
        float4 xv = xr[lane + q * 32], wv = w4[lane + q * 32];
        s += xv.x * wv.x + xv.y * wv.y + xv.z * wv.z + xv.w * wv.w;
    }
#pragma unroll
    for (int o = 16; o; o >>= 1) s += __shfl_xor_sync(0xffffffffu, s, o);
    if (lane == 0) {
        const int b = row >> 10, i = row & (NI - 1);
        float tot = s + bA[0];
        g_faT[i * BB + b] = 1.f / (1.f + __expf(-tot));
    }
}

// ---------------- K2: phi0 transposed [j][i][b] ---------------------------
__global__ __launch_bounds__(256) void k_phi0(const float* __restrict__ bu,
                                              const float* __restrict__ bn) {
    const int p = blockIdx.x * 256 + threadIdx.x;
    const int j = p >> 10, i = p & (NI - 1);
    const float cu = bu[i * NOUT + j] * (1.0f / 64.0f) - bn[i * NOUT + j] * (63.0f / 64.0f);
    const float4* fa = reinterpret_cast<const float4*>(&g_faT[i * BB]);
    float4* dst = reinterpret_cast<float4*>(&g_phiT[((size_t)j * NI + i) * BB]);
#pragma unroll
    for (int q = 0; q < 8; q++) {
        float4 v = fa[q];
        dst[q] = make_float4(v.x * cu, v.y * cu, v.z * cu, v.w * cu);
    }
}

// ---------------- K3 (TENSOR, proven): out = phiT . Wm --------------------
#define AMP 40
#define BNP 136
template <int MODE>
__global__ __launch_bounds__(128) void k_mem(const float* __restrict__ Wm,
                                             float* __restrict__ outp) {
    const int j = blockIdx.y, hb = blockIdx.x;
    __shared__ __align__(16) uint16_t Ah[2][32][AMP], Al[2][32][AMP];
    __shared__ __align__(16) uint16_t Bh[2][32][BNP], Bl[2][32][BNP];
    const int tid = threadIdx.x, lane = tid & 31, w = tid >> 5;
    const int fr = tid >> 2, fq = tid & 3;
    const int g = lane >> 3, r = lane & 7;
    const float* WmB = Wm + (size_t)j * DOUT + (size_t)hb * 128;
    const float* Ab = g_phiT + (size_t)j * (NI * BB);

    float c[2][4][4];
#pragma unroll
    for (int mt = 0; mt < 2; mt++)
#pragma unroll
        for (int nt = 0; nt < 4; nt++)
#pragma unroll
            for (int e = 0; e < 4; e++) c[mt][nt][e] = 0.f;

    float4 bR[8], aR[2];
    {
        const float* br = WmB + (size_t)fr * (NOUT * DOUT);
#pragma unroll
        for (int q = 0; q < 8; q++)
            bR[q] = *reinterpret_cast<const float4*>(br + (size_t)(fq + q * 4) * 4);
        const float* ar = Ab + (size_t)fr * BB + fq * 8;
        aR[0] = *reinterpret_cast<const float4*>(ar);
        aR[1] = *reinterpret_cast<const float4*>(ar + 4);
    }
    {
#pragma unroll
        for (int q = 0; q < 8; q++) {
            uint2 hi, lo; cvt_split(bR[q], hi, lo);
            const int n = (fq + q * 4) * 4;
            *reinterpret_cast<uint2*>(&Bh[0][fr][n]) = hi;
            *reinterpret_cast<uint2*>(&Bl[0][fr][n]) = lo;
        }
        uint2 h0, l0, h1, l1;
        cvt_split(aR[0], h0, l0); cvt_split(aR[1], h1, l1);
        const int m = fq * 8;
        *reinterpret_cast<uint4*>(&Ah[0][fr][m]) = make_uint4(h0.x, h0.y, h1.x, h1.y);
        *reinterpret_cast<uint4*>(&Al[0][fr][m]) = make_uint4(l0.x, l0.y, l1.x, l1.y);
    }
    __syncthreads();

    const int NSTG = NI / 32;
    for (int t = 0; t < NSTG; t++) {
        const int cur = t & 1;
        const bool more = (t + 1 < NSTG);
        if (more) {
            const int i0 = (t + 1) * 32;
            const float* br = WmB + (size_t)(i0 + fr) * (NOUT * DOUT);
#pragma unroll
            for (int q = 0; q < 8; q++)
                bR[q] = *reinterpret_cast<const float4*>(br + (size_t)(fq + q * 4) * 4);
            const float* ar = Ab + (size_t)(i0 + fr) * BB + fq * 8;
            aR[0] = *reinterpret_cast<const float4*>(ar);
            aR[1] = *reinterpret_cast<const float4*>(ar + 4);
        }
#pragma unroll
        for (int kk = 0; kk < 32; kk += 16) {
            uint32_t ah[2][4], al[2][4], bh[4][2], bl[4][2];
#pragma unroll
            for (int mt = 0; mt < 2; mt++) {
                const int ak = kk + (g >> 1) * 8 + r, am = mt * 16 + (g & 1) * 8;
                ldsm4t(ah[mt][0], ah[mt][1], ah[mt][2], ah[mt][3],
                       smem_u32(&Ah[cur][ak][am]));
                ldsm4t(al[mt][0], al[mt][1], al[mt][2], al[mt][3],
                       smem_u32(&Al[cur][ak][am]));
            }
#pragma unroll
            for (int p = 0; p < 2; p++) {
                const int bk = kk + (g & 1) * 8 + r;
                const int bn = w * 32 + p * 16 + (g >> 1) * 8;
                ldsm4t(bh[2 * p][0], bh[2 * p][1], bh[2 * p + 1][0], bh[2 * p + 1][1],
                       smem_u32(&Bh[cur][bk][bn]));
                ldsm4t(bl[2 * p][0], bl[2 * p][1], bl[2 * p + 1][0], bl[2 * p + 1][1],
                       smem_u32(&Bl[cur][bk][bn]));
            }
#pragma unroll
            for (int mt = 0; mt < 2; mt++)
#pragma unroll
                for (int nt = 0; nt < 4; nt++) {
                    mma_bf16(c[mt][nt], ah[mt], bh[nt][0], bh[nt][1]);
                    mma_bf16(c[mt][nt], ah[mt], bl[nt][0], bl[nt][1]);
                    mma_bf16(c[mt][nt], al[mt], bh[nt][0], bh[nt][1]);
                }
        }
        if (more) {
            const int nxt = 1 - cur;
#pragma unroll
            for (int q = 0; q < 8; q++) {
                uint2 hi, lo; cvt_split(bR[q], hi, lo);
                const int n = (fq + q * 4) * 4;
                *reinterpret_cast<uint2*>(&Bh[nxt][fr][n]) = hi;
                *reinterpret_cast<uint2*>(&Bl[nxt][fr][n]) = lo;
            }
            uint2 h0, l0, h1, l1;
            cvt_split(aR[0], h0, l0); cvt_split(aR[1], h1, l1);
            const int m = fq * 8;
            *reinterpret_cast<uint4*>(&Ah[nxt][fr][m]) = make_uint4(h0.x, h0.y, h1.x, h1.y);
            *reinterpret_cast<uint4*>(&Al[nxt][fr][m]) = make_uint4(l0.x, l0.y, l1.x, l1.y);
        }
        __syncthreads();
    }

    float* dst = (MODE == 0) ? g_xout0 : outp;
#pragma unroll
    for (int mt = 0; mt < 2; mt++)
#pragma unroll
        for (int nt = 0; nt < 4; nt++) {
            const int m0 = mt * 16 + (lane >> 2);
            const int n = hb * 128 + w * 32 + nt * 8 + (lane & 3) * 2;
            float* o0 = dst + ((size_t)(m0 * NOUT + j)) * DOUT + n;
            *reinterpret_cast<float2*>(o0) = make_float2(c[mt][nt][0], c[mt][nt][1]);
            float* o1 = dst + ((size_t)((m0 + 8) * NOUT + j)) * DOUT + n;
            *reinterpret_cast<float2*>(o1) = make_float2(c[mt][nt][2], c[mt][nt][3]);
        }
}

// ---------------- K4 (TENSOR, split-K, 64x64 warp tile): pred partials ----
// Grid (nb 0..7, mb 0..15, ks 0..3) = 512 CTAs, 128 thr.
// CTA tile 128m x 128n, warps 2x2 (wm = w&1, wn = w>>1), warp tile 64m x 64n.
// Per warp-k16: 16 ldsm (64 wf) / 96 MMAs -> wf/MMA = 0.67.
#define PKP 24
__global__ __launch_bounds__(128) void k_predp(const float* __restrict__ WG) {
    const int nb = blockIdx.x, mb = blockIdx.y, ks = blockIdx.z;
    const int mBase = mb * 128, nBase = nb * 128, kBase = ks * 256;
    __shared__ __align__(16) uint16_t Ah[2][128][PKP], Al[2][128][PKP];
    __shared__ __align__(16) uint16_t Bh[2][16][BNP], Bl[2][16][BNP];
    const int tid = threadIdx.x, lane = tid & 31, w = tid >> 5;
    const int wm = w & 1, wn = w >> 1;
    const int g = lane >> 3, r = lane & 7;
    const int fbr = tid >> 3, fbn = tid & 7;
    const int arow = lane & 15, acol = (lane >> 4) * 8;

    float c[4][8][4];
#pragma unroll
    for (int mt = 0; mt < 4; mt++)
#pragma unroll
        for (int nt = 0; nt < 8; nt++)
#pragma unroll
            for (int e = 0; e < 4; e++) c[mt][nt][e] = 0.f;

    float4 aR[4], bR[4];
#pragma unroll
    for (int q = 0; q < 4; q++)
        aR[q] = *reinterpret_cast<const float4*>(g_xout0 + (size_t)(mBase + tid) * DOUT + kBase + q * 4);
#pragma unroll
    for (int q = 0; q < 4; q++)
        bR[q] = *reinterpret_cast<const float4*>(WG + (size_t)(kBase + fbr) * DIN + nBase + (size_t)(fbn + q * 8) * 4);
    {
#pragma unroll
        for (int q = 0; q < 4; q++) {
            uint2 hi, lo; cvt_split(aR[q], hi, lo);
            *reinterpret_cast<uint2*>(&Ah[0][tid][q * 4]) = hi;
            *reinterpret_cast<uint2*>(&Al[0][tid][q * 4]) = lo;
        }
#pragma unroll
        for (int q = 0; q < 4; q++) {
            uint2 hi, lo; cvt_split(bR[q], hi, lo);
            const int n = (fbn + q * 8) * 4;
            *reinterpret_cast<uint2*>(&Bh[0][fbr][n]) = hi;
            *reinterpret_cast<uint2*>(&Bl[0][fbr][n]) = lo;
        }
    }
    __syncthreads();

    const int NSTG = 256 / 16;  // 16
    for (int t = 0; t < NSTG; t++) {
        const int cur = t & 1;
        const bool more = (t + 1 < NSTG);
        if (more) {
            const int k0 = kBase + (t + 1) * 16;
#pragma unroll
            for (int q = 0; q < 4; q++)
                aR[q] = *reinterpret_cast<const float4*>(g_xout0 + (size_t)(mBase + tid) * DOUT + k0 + q * 4);
#pragma unroll
            for (int q = 0; q < 4; q++)
                bR[q] = *reinterpret_cast<const float4*>(WG + (size_t)(k0 + fbr) * DIN + nBase + (size_t)(fbn + q * 8) * 4);
        }
        {
            uint32_t ah[4][4], al[4][4], bh[8][2], bl[8][2];
#pragma unroll
            for (int mt = 0; mt < 4; mt++) {
                const int am = wm * 64 + mt * 16 + arow;
                ldsm4(ah[mt][0], ah[mt][1], ah[mt][2], ah[mt][3],
                      smem_u32(&Ah[cur][am][acol]));
                ldsm4(al[mt][0], al[mt][1], al[mt][2], al[mt][3],
                      smem_u32(&Al[cur][am][acol]));
            }
#pragma unroll
            for (int p = 0; p < 4; p++) {
                const int bk = (g & 1) * 8 + r;
                const int bn = wn * 64 + p * 16 + (g >> 1) * 8;
                ldsm4t(bh[2 * p][0], bh[2 * p][1], bh[2 * p + 1][0], bh[2 * p + 1][1],
                       smem_u32(&Bh[cur][bk][bn]));
                ldsm4t(bl[2 * p][0], bl[2 * p][1], bl[2 * p + 1][0], bl[2 * p + 1][1],
                       smem_u32(&Bl[cur][bk][bn]));
            }
#pragma unroll
            for (int mt = 0; mt < 4; mt++)
#pragma unroll
                for (int nt = 0; nt < 8; nt++) {
                    mma_bf16(c[mt][nt], ah[mt], bh[nt][0], bh[nt][1]);
                    mma_bf16(c[mt][nt], ah[mt], bl[nt][0], bl[nt][1]);
                    mma_bf16(c[mt][nt], al[mt], bh[nt][0], bh[nt][1]);
                }
        }
        if (more) {
            const int nxt = 1 - cur;
#pragma unroll
            for (int q = 0; q < 4; q++) {
                uint2 hi, lo; cvt_split(aR[q], hi, lo);
                *reinterpret_cast<uint2*>(&Ah[nxt][tid][q * 4]) = hi;
                *reinterpret_cast<uint2*>(&Al[nxt][tid][q * 4]) = lo;
            }
#pragma unroll
            for (int q = 0; q < 4; q++) {
                uint2 hi, lo; cvt_split(bR[q], hi, lo);
                const int n = (fbn + q * 8) * 4;
                *reinterpret_cast<uint2*>(&Bh[nxt][fbr][n]) = hi;
                *reinterpret_cast<uint2*>(&Bl[nxt][fbr][n]) = lo;
            }
        }
        __syncthreads();
    }

    float* dst = g_ppart[ks];
#pragma unroll
    for (int nt = 0; nt < 8; nt++) {
        const int n = nBase + wn * 64 + nt * 8 + (lane & 3) * 2;
#pragma unroll
        for (int mt = 0; mt < 4; mt++) {
            const int m0 = mBase + wm * 64 + mt * 16 + (lane >> 2);
            *reinterpret_cast<float2*>(dst + (size_t)m0 * DIN + n) =
                make_float2(c[mt][nt][0], c[mt][nt][1]);
            *reinterpret_cast<float2*>(dst + (size_t)(m0 + 8) * DIN + n) =
                make_float2(c[mt][nt][2], c[mt][nt][3]);
        }
    }
}

// ---------------- K4b: combine partials + bias -> g_pred ------------------
__global__ __launch_bounds__(256) void k_comb(const float* __restrict__ bG) {
    const int idx = blockIdx.x * 256 + threadIdx.x;
    const int S = BB * NOUT * DIN / 4;
    const float4* p = reinterpret_cast<const float4*>(g_ppart);
    float4 a = p[idx], b2 = p[idx + S], c2 = p[idx + 2 * S], d = p[idx + 3 * S];
    const float4 bg = reinterpret_cast<const float4*>(bG)[idx & (DIN / 4 - 1)];
    reinterpret_cast<float4*>(g_pred)[idx] = make_float4(
        a.x + b2.x + c2.x + d.x + bg.x, a.y + b2.y + c2.y + d.y + bg.y,
        a.z + b2.z + c2.z + d.z + bg.z, a.w + b2.w + c2.w + d.w + bg.w);
}

// ---------------- K5 (TENSOR, round-10 proven): S -> softmax -> phi1 ------
__global__ __launch_bounds__(128) void k_sim(const float* __restrict__ x,
                                             const float* __restrict__ bu,
                                             const float* __restrict__ bn) {
    const int i0 = blockIdx.x * 128;
    const int b = blockIdx.y;
    __shared__ __align__(16) uint16_t Ah[2][128][PKP], Al[2][128][PKP];
    __shared__ __align__(16) uint16_t Bh[2][NOUT][PKP], Bl[2][NOUT][PKP];
    const int tid = threadIdx.x, lane = tid & 31, w = tid >> 5;
    const int fbj = tid & 63, fbk = (tid >> 6) * 8;
    const int arow = lane & 15, acol = (lane >> 4) * 8;
    const int brow = ((lane >> 4) & 1) * 8 + (lane & 7), bcol = ((lane >> 3) & 1) * 8;

    const float* Arow = x + ((size_t)b * NI + i0 + tid) * DIN;
    const float* Brow = g_pred + ((size_t)b * NOUT + fbj) * DIN;

    float c[2][8][4];
#pragma unroll
    for (int mt = 0; mt < 2; mt++)
#pragma unroll
        for (int nt = 0; nt < 8; nt++)
#pragma unroll
            for (int e = 0; e < 4; e++) c[mt][nt][e] = 0.f;

    float4 aR[4]; float4 bR[2];
#pragma unroll
    for (int q = 0; q < 4; q++)
        aR[q] = *reinterpret_cast<const float4*>(Arow + q * 4);
#pragma unroll
    for (int q = 0; q < 2; q++)
        bR[q] = *reinterpret_cast<const float4*>(Brow + fbk + q * 4);
    {
#pragma unroll
        for (int q = 0; q < 4; q++) {
            uint2 hi, lo; cvt_split(aR[q], hi, lo);
            *reinterpret_cast<uint2*>(&Ah[0][tid][q * 4]) = hi;
            *reinterpret_cast<uint2*>(&Al[0][tid][q * 4]) = lo;
        }
#pragma unroll
        for (int q = 0; q < 2; q++) {
            uint2 hi, lo; cvt_split(bR[q], hi, lo);
            *reinterpret_cast<uint2*>(&Bh[0][fbj][fbk + q * 4]) = hi;
            *reinterpret_cast<uint2*>(&Bl[0][fbj][fbk + q * 4]) = lo;
        }
    }
    __syncthreads();

    const int NSTG = DIN / 16;
    for (int t = 0; t < NSTG; t++) {
        const int cur = t & 1;
        const bool more = (t + 1 < NSTG);
        if (more) {
            const int d0 = (t + 1) * 16;
#pragma unroll
            for (int q = 0; q < 4; q++)
                aR[q] = *reinterpret_cast<const float4*>(Arow + d0 + q * 4);
#pragma unroll
            for (int q = 0; q < 2; q++)
                bR[q] = *reinterpret_cast<const float4*>(Brow + d0 + fbk + q * 4);
        }
        {
            uint32_t ah[2][4], al[2][4], bh[8][2], bl[8][2];
#pragma unroll
            for (int mt = 0; mt < 2; mt++) {
                const int am = w * 32 + mt * 16 + arow;
                ldsm4(ah[mt][0], ah[mt][1], ah[mt][2], ah[mt][3],
                      smem_u32(&Ah[cur][am][acol]));
                ldsm4(al[mt][0], al[mt][1], al[mt][2], al[mt][3],
                      smem_u32(&Al[cur][am][acol]));
            }
#pragma unroll
            for (int p = 0; p < 4; p++) {
                const int bj = p * 16 + brow;
                ldsm4(bh[2 * p][0], bh[2 * p][1], bh[2 * p + 1][0], bh[2 * p + 1][1],
                      smem_u32(&Bh[cur][bj][bcol]));
                ldsm4(bl[2 * p][0], bl[2 * p][1], bl[2 * p + 1][0], bl[2 * p + 1][1],
                      smem_u32(&Bl[cur][bj][bcol]));
            }
#pragma unroll
            for (int mt = 0; mt < 2; mt++)
#pragma unroll
                for (int nt = 0; nt < 8; nt++) {
                    mma_bf16(c[mt][nt], ah[mt], bh[nt][0], bh[nt][1]);
                    mma_bf16(c[mt][nt], ah[mt], bl[nt][0], bl[nt][1]);
                    mma_bf16(c[mt][nt], al[mt], bh[nt][0], bh[nt][1]);
                }
        }
        if (more) {
            const int nxt = 1 - cur;
#pragma unroll
            for (int q = 0; q < 4; q++) {
                uint2 hi, lo; cvt_split(aR[q], hi, lo);
                *reinterpret_cast<uint2*>(&Ah[nxt][tid][q * 4]) = hi;
                *reinterpret_cast<uint2*>(&Al[nxt][tid][q * 4]) = lo;
            }
#pragma unroll
            for (int q = 0; q < 2; q++) {
                uint2 hi, lo; cvt_split(bR[q], hi, lo);
                *reinterpret_cast<uint2*>(&Bh[nxt][fbj][fbk + q * 4]) = hi;
                *reinterpret_cast<uint2*>(&Bl[nxt][fbj][fbk + q * 4]) = lo;
            }
        }
        __syncthreads();
    }

    const float scale = 0.03125f;  // 1024^-0.5
#pragma unroll
    for (int mt = 0; mt < 2; mt++) {
#pragma unroll
        for (int half = 0; half < 2; half++) {
            const int rg = i0 + w * 32 + mt * 16 + (lane >> 2) + half * 8;
            float v[16];
#pragma unroll
            for (int nt = 0; nt < 8; nt++) {
                v[nt * 2 + 0] = c[mt][nt][half * 2 + 0] * scale;
                v[nt * 2 + 1] = c[mt][nt][half * 2 + 1] * scale;
            }
            float mx = v[0];
#pragma unroll
            for (int q = 1; q < 16; q++) mx = fmaxf(mx, v[q]);
            mx = fmaxf(mx, __shfl_xor_sync(0xffffffffu, mx, 1));
            mx = fmaxf(mx, __shfl_xor_sync(0xffffffffu, mx, 2));
            float e[16], s = 0.f;
#pragma unroll
            for (int q = 0; q < 16; q++) { e[q] = __expf(v[q] - mx); s += e[q]; }
            s += __shfl_xor_sync(0xffffffffu, s, 1);
            s += __shfl_xor_sync(0xffffffffu, s, 2);
            const float inv = 1.f / s;
            const float fa = g_faT[rg * BB + b];
            float* o = g_phi1 + ((size_t)b * NI + rg) * NOUT;
#pragma unroll
            for (int nt = 0; nt < 8; nt++) {
                const int jj = nt * 8 + (lane & 3) * 2;
                const float2 bu2 = *reinterpret_cast<const float2*>(bu + (size_t)rg * NOUT + jj);
                const float2 bn2 = *reinterpret_cast<const float2*>(bn + (size_t)rg * NOUT + jj);
                *reinterpret_cast<float2*>(o + jj) = make_float2(
                    fa * ((bu2.x + bn2.x) * e[nt * 2 + 0] * inv - bn2.x),
                    fa * ((bu2.y + bn2.y) * e[nt * 2 + 1] * inv - bn2.y));
            }
        }
    }
}

// ---------------- K6: transpose phi1 [b][i][j] -> phiT [j][i][b] ----------
__global__ __launch_bounds__(256) void k_tr() {
    const int i = blockIdx.x;
    __shared__ float t[32][65];
    const int tid = threadIdx.x;
#pragma unroll
    for (int q = 0; q < 8; q++) {
        int idx = tid + q * 256;
        int bb = idx >> 6, j = idx & 63;
        t[bb][j] = g_phi1[((size_t)bb * NI + i) * NOUT + j];
    }
    __syncthreads();
#pragma unroll
    for (int q = 0; q < 8; q++) {
        int idx = tid + q * 256;
        int j = idx >> 5, bb = idx & 31;
        g_phiT[((size_t)j * NI + i) * BB + bb] = t[bb][j];
    }
}

// ---------------- launch ---------------------------------------------------
extern "C" void kernel_launch(void* const* d_in, const int* in_sizes, int n_in,
                              void* d_out, int out_size) {
    const float* x  = (const float*)d_in[0];
    const float* WA = (const float*)d_in[1];
    const float* bA = (const float*)d_in[2];
    const float* Wm = (const float*)d_in[3];
    const float* WG = (const float*)d_in[4];
    const float* bG = (const float*)d_in[5];
    const float* bu = (const float*)d_in[6];
    const float* bn = (const float*)d_in[7];
    float* out = (float*)d_out;

    k_fa<<<4096, 256>>>(x, WA, bA);
    k_phi0<<<256, 256>>>(bu, bn);
    k_mem<0><<<dim3(8, 64), 128>>>(Wm, nullptr);
    k_predp<<<dim3(8, 16, 4), 128>>>(WG);
    k_comb<<<BB * NOUT * DIN / 1024, 256>>>(bG);
    k_sim<<<dim3(8, 32), 128>>>(x, bu, bn);
    k_tr<<<NI, 256>>>();
    k_mem<1><<<dim3(8, 64), 128>>>(Wm, out);
}

// round 16
// speedup vs baseline: 1.0685x; 1.0246x over previous
#include <cuda_runtime.h>
#include <cuda_bf16.h>
#include <cstdint>

#define BB 32
#define NI 1024
#define DIN 1024
#define NOUT 64
#define DOUT 1024

// ---------------- device scratch ----------------
__device__ float g_faT[NI * BB];              // f_a transposed [i][b]
__device__ float g_xout0[BB * NOUT * DOUT];   // iter-0 output [b][j][h]
__device__ float g_pred[BB * NOUT * DIN];     // pred [b][j][d]
__device__ float g_phi1[BB * NI * NOUT];      // phi iter-1 [b][i][j]
__device__ float g_phiT[NOUT * NI * BB];      // phi transposed [j][i][b]
__device__ float g_ppart[4][BB * NOUT * DIN]; // k_pred split-K partials

// ---------------- mma helpers ----------------
__device__ __forceinline__ uint32_t smem_u32(const void* p) {
    return (uint32_t)__cvta_generic_to_shared(p);
}
__device__ __forceinline__ void ldsm4(uint32_t& r0, uint32_t& r1, uint32_t& r2,
                                      uint32_t& r3, uint32_t a) {
    asm volatile("ldmatrix.sync.aligned.m8n8.x4.shared.b16 {%0,%1,%2,%3}, [%4];"
                 : "=r"(r0), "=r"(r1), "=r"(r2), "=r"(r3) : "r"(a));
}
__device__ __forceinline__ void ldsm4t(uint32_t& r0, uint32_t& r1, uint32_t& r2,
                                       uint32_t& r3, uint32_t a) {
    asm volatile("ldmatrix.sync.aligned.m8n8.x4.trans.shared.b16 {%0,%1,%2,%3}, [%4];"
                 : "=r"(r0), "=r"(r1), "=r"(r2), "=r"(r3) : "r"(a));
}
__device__ __forceinline__ void mma_bf16(float* c, const uint32_t* a,
                                         uint32_t b0, uint32_t b1) {
    asm volatile("mma.sync.aligned.m16n8k16.row.col.f32.bf16.bf16.f32 "
                 "{%0,%1,%2,%3}, {%4,%5,%6,%7}, {%8,%9}, {%0,%1,%2,%3};"
                 : "+f"(c[0]), "+f"(c[1]), "+f"(c[2]), "+f"(c[3])
                 : "r"(a[0]), "r"(a[1]), "r"(a[2]), "r"(a[3]), "r"(b0), "r"(b1));
}
__device__ __forceinline__ uint32_t packbf(__nv_bfloat16 a, __nv_bfloat16 b) {
    return (uint32_t)__bfloat16_as_ushort(a) | ((uint32_t)__bfloat16_as_ushort(b) << 16);
}
__device__ __forceinline__ void cvt_split(float4 v, uint2& hi, uint2& lo) {
    __nv_bfloat16 hx = __float2bfloat16(v.x), hy = __float2bfloat16(v.y);
    __nv_bfloat16 hz = __float2bfloat16(v.z), hw = __float2bfloat16(v.w);
    __nv_bfloat16 lx = __float2bfloat16(v.x - __bfloat162float(hx));
    __nv_bfloat16 ly = __float2bfloat16(v.y - __bfloat162float(hy));
    __nv_bfloat16 lz = __float2bfloat16(v.z - __bfloat162float(hz));
    __nv_bfloat16 lw = __float2bfloat16(v.w - __bfloat162float(hw));
    hi.x = packbf(hx, hy); hi.y = packbf(hz, hw);
    lo.x = packbf(lx, ly); lo.y = packbf(lz, lw);
}

// ---------------- K1: f_a = sigmoid(x . W_A + b_A) -> g_faT[i][b] ---------
__global__ __launch_bounds__(256) void k_fa(const float* __restrict__ x,
                                            const float* __restrict__ WA,
                                            const float* __restrict__ bA) {
    const int row = blockIdx.x * 8 + (threadIdx.x >> 5);
    const int lane = threadIdx.x & 31;
    const float4* xr = reinterpret_cast<const float4*>(x) + (size_t)row * (DIN / 4);
    const float4* w4 = reinterpret_cast<const float4*>(WA);
    float s = 0.f;
#pragma unroll
    for (int q = 0; q < 8; q++) {
        float4 xv = xr[lane + q * 32], wv = w4[lane + q * 32];
        s += xv.x * wv.x + xv.y * wv.y + xv.z * wv.z + xv.w * wv.w;
    }
#pragma unroll
    for (int o = 16; o; o >>= 1) s += __shfl_xor_sync(0xffffffffu, s, o);
    if (lane == 0) {
        const int b = row >> 10, i = row & (NI - 1);
        float tot = s + bA[0];
        g_faT[i * BB + b] = 1.f / (1.f + __expf(-tot));
    }
}

// ---------------- K2: phi0 transposed [j][i][b] ---------------------------
__global__ __launch_bounds__(256) void k_phi0(const float* __restrict__ bu,
                                              const float* __restrict__ bn) {
    const int p = blockIdx.x * 256 + threadIdx.x;
    const int j = p >> 10, i = p & (NI - 1);
    const float cu = bu[i * NOUT + j] * (1.0f / 64.0f) - bn[i * NOUT + j] * (63.0f / 64.0f);
    const float4* fa = reinterpret_cast<const float4*>(&g_faT[i * BB]);
    float4* dst = reinterpret_cast<float4*>(&g_phiT[((size_t)j * NI + i) * BB]);
#pragma unroll
    for (int q = 0; q < 8; q++) {
        float4 v = fa[q];
        dst[q] = make_float4(v.x * cu, v.y * cu, v.z * cu, v.w * cu);
    }
}

// ---------------- K3 (TENSOR): out = phiT . Wm  (128B-coalesced B loads) --
// Grid (hb 0..7, j 0..63), 128 thr. Tile 32b x 128h, stage K=32.
// B staging ported from proven k_predp pattern: 8 thr x 16B = 128B per row.
#define AMP 40
#define BNP 136
template <int MODE>
__global__ __launch_bounds__(128) void k_mem(const float* __restrict__ Wm,
                                             float* __restrict__ outp) {
    const int j = blockIdx.y, hb = blockIdx.x;
    __shared__ __align__(16) uint16_t Ah[2][32][AMP], Al[2][32][AMP];
    __shared__ __align__(16) uint16_t Bh[2][32][BNP], Bl[2][32][BNP];
    const int tid = threadIdx.x, lane = tid & 31, w = tid >> 5;
    const int fbr = tid >> 3, fbn = tid & 7;        // B: rows 0..15 (+16), 128B groups
    const int far_ = tid >> 2, fac = (tid & 3) * 8; // A: rows 0..31, 2 f4 (128B/row)
    const int g = lane >> 3, r = lane & 7;
    const float* WmB = Wm + (size_t)j * DOUT + (size_t)hb * 128;
    const float* Ab = g_phiT + (size_t)j * (NI * BB);

    float c[2][4][4];
#pragma unroll
    for (int mt = 0; mt < 2; mt++)
#pragma unroll
        for (int nt = 0; nt < 4; nt++)
#pragma unroll
            for (int e = 0; e < 4; e++) c[mt][nt][e] = 0.f;

    float4 bR[8], aR[2];
    {
#pragma unroll
        for (int h = 0; h < 2; h++) {
            const float* br = WmB + (size_t)(fbr + h * 16) * (NOUT * DOUT);
#pragma unroll
            for (int q = 0; q < 4; q++)
                bR[h * 4 + q] = *reinterpret_cast<const float4*>(br + (size_t)(fbn + q * 8) * 4);
        }
        const float* ar = Ab + (size_t)far_ * BB + fac;
        aR[0] = *reinterpret_cast<const float4*>(ar);
        aR[1] = *reinterpret_cast<const float4*>(ar + 4);
    }
    {
#pragma unroll
        for (int h = 0; h < 2; h++)
#pragma unroll
            for (int q = 0; q < 4; q++) {
                uint2 hi, lo; cvt_split(bR[h * 4 + q], hi, lo);
                const int n = (fbn + q * 8) * 4;
                *reinterpret_cast<uint2*>(&Bh[0][fbr + h * 16][n]) = hi;
                *reinterpret_cast<uint2*>(&Bl[0][fbr + h * 16][n]) = lo;
            }
        uint2 h0, l0, h1, l1;
        cvt_split(aR[0], h0, l0); cvt_split(aR[1], h1, l1);
        const int m = fac;
        *reinterpret_cast<uint4*>(&Ah[0][far_][m]) = make_uint4(h0.x, h0.y, h1.x, h1.y);
        *reinterpret_cast<uint4*>(&Al[0][far_][m]) = make_uint4(l0.x, l0.y, l1.x, l1.y);
    }
    __syncthreads();

    const int NSTG = NI / 32;
    for (int t = 0; t < NSTG; t++) {
        const int cur = t & 1;
        const bool more = (t + 1 < NSTG);
        if (more) {
            const int i0 = (t + 1) * 32;
#pragma unroll
            for (int h = 0; h < 2; h++) {
                const float* br = WmB + (size_t)(i0 + fbr + h * 16) * (NOUT * DOUT);
#pragma unroll
                for (int q = 0; q < 4; q++)
                    bR[h * 4 + q] = *reinterpret_cast<const float4*>(br + (size_t)(fbn + q * 8) * 4);
            }
            const float* ar = Ab + (size_t)(i0 + far_) * BB + fac;
            aR[0] = *reinterpret_cast<const float4*>(ar);
            aR[1] = *reinterpret_cast<const float4*>(ar + 4);
        }
#pragma unroll
        for (int kk = 0; kk < 32; kk += 16) {
            uint32_t ah[2][4], al[2][4], bh[4][2], bl[4][2];
#pragma unroll
            for (int mt = 0; mt < 2; mt++) {
                const int ak = kk + (g >> 1) * 8 + r, am = mt * 16 + (g & 1) * 8;
                ldsm4t(ah[mt][0], ah[mt][1], ah[mt][2], ah[mt][3],
                       smem_u32(&Ah[cur][ak][am]));
                ldsm4t(al[mt][0], al[mt][1], al[mt][2], al[mt][3],
                       smem_u32(&Al[cur][ak][am]));
            }
#pragma unroll
            for (int p = 0; p < 2; p++) {
                const int bk = kk + (g & 1) * 8 + r;
                const int bn = w * 32 + p * 16 + (g >> 1) * 8;
                ldsm4t(bh[2 * p][0], bh[2 * p][1], bh[2 * p + 1][0], bh[2 * p + 1][1],
                       smem_u32(&Bh[cur][bk][bn]));
                ldsm4t(bl[2 * p][0], bl[2 * p][1], bl[2 * p + 1][0], bl[2 * p + 1][1],
                       smem_u32(&Bl[cur][bk][bn]));
            }
#pragma unroll
            for (int mt = 0; mt < 2; mt++)
#pragma unroll
                for (int nt = 0; nt < 4; nt++) {
                    mma_bf16(c[mt][nt], ah[mt], bh[nt][0], bh[nt][1]);
                    mma_bf16(c[mt][nt], ah[mt], bl[nt][0], bl[nt][1]);
                    mma_bf16(c[mt][nt], al[mt], bh[nt][0], bh[nt][1]);
                }
        }
        if (more) {
            const int nxt = 1 - cur;
#pragma unroll
            for (int h = 0; h < 2; h++)
#pragma unroll
                for (int q = 0; q < 4; q++) {
                    uint2 hi, lo; cvt_split(bR[h * 4 + q], hi, lo);
                    const int n = (fbn + q * 8) * 4;
                    *reinterpret_cast<uint2*>(&Bh[nxt][fbr + h * 16][n]) = hi;
                    *reinterpret_cast<uint2*>(&Bl[nxt][fbr + h * 16][n]) = lo;
                }
            uint2 h0, l0, h1, l1;
            cvt_split(aR[0], h0, l0); cvt_split(aR[1], h1, l1);
            *reinterpret_cast<uint4*>(&Ah[nxt][far_][fac]) = make_uint4(h0.x, h0.y, h1.x, h1.y);
            *reinterpret_cast<uint4*>(&Al[nxt][far_][fac]) = make_uint4(l0.x, l0.y, l1.x, l1.y);
        }
        __syncthreads();
    }

    float* dst = (MODE == 0) ? g_xout0 : outp;
#pragma unroll
    for (int mt = 0; mt < 2; mt++)
#pragma unroll
        for (int nt = 0; nt < 4; nt++) {
            const int m0 = mt * 16 + (lane >> 2);
            const int n = hb * 128 + w * 32 + nt * 8 + (lane & 3) * 2;
            float* o0 = dst + ((size_t)(m0 * NOUT + j)) * DOUT + n;
            *reinterpret_cast<float2*>(o0) = make_float2(c[mt][nt][0], c[mt][nt][1]);
            float* o1 = dst + ((size_t)((m0 + 8) * NOUT + j)) * DOUT + n;
            *reinterpret_cast<float2*>(o1) = make_float2(c[mt][nt][2], c[mt][nt][3]);
        }
}

// ---------------- K4 (TENSOR, split-K): pred partials ---------------------
#define PKP 24
__global__ __launch_bounds__(128) void k_predp(const float* __restrict__ WG) {
    const int nb = blockIdx.x, mb = blockIdx.y, ks = blockIdx.z;
    const int mBase = mb * 64, nBase = nb * 128, kBase = ks * 256;
    __shared__ __align__(16) uint16_t Ah[2][64][PKP], Al[2][64][PKP];
    __shared__ __align__(16) uint16_t Bh[2][16][BNP], Bl[2][16][BNP];
    const int tid = threadIdx.x, lane = tid & 31, w = tid >> 5;
    const int g = lane >> 3, r = lane & 7;
    const int fam = tid & 63, fak = (tid >> 6) * 8;
    const int fbr = tid >> 3, fbn = tid & 7;
    const int arow = lane & 15, acol = (lane >> 4) * 8;

    float c[4][4][4];
#pragma unroll
    for (int mt = 0; mt < 4; mt++)
#pragma unroll
        for (int nt = 0; nt < 4; nt++)
#pragma unroll
            for (int e = 0; e < 4; e++) c[mt][nt][e] = 0.f;

    float4 aR[2], bR[4];
#pragma unroll
    for (int q = 0; q < 2; q++)
        aR[q] = *reinterpret_cast<const float4*>(g_xout0 + (size_t)(mBase + fam) * DOUT + kBase + fak + q * 4);
#pragma unroll
    for (int q = 0; q < 4; q++)
        bR[q] = *reinterpret_cast<const float4*>(WG + (size_t)(kBase + fbr) * DIN + nBase + (size_t)(fbn + q * 8) * 4);
    {
#pragma unroll
        for (int q = 0; q < 2; q++) {
            uint2 hi, lo; cvt_split(aR[q], hi, lo);
            *reinterpret_cast<uint2*>(&Ah[0][fam][fak + q * 4]) = hi;
            *reinterpret_cast<uint2*>(&Al[0][fam][fak + q * 4]) = lo;
        }
#pragma unroll
        for (int q = 0; q < 4; q++) {
            uint2 hi, lo; cvt_split(bR[q], hi, lo);
            const int n = (fbn + q * 8) * 4;
            *reinterpret_cast<uint2*>(&Bh[0][fbr][n]) = hi;
            *reinterpret_cast<uint2*>(&Bl[0][fbr][n]) = lo;
        }
    }
    __syncthreads();

    const int NSTG = 256 / 16;
    for (int t = 0; t < NSTG; t++) {
        const int cur = t & 1;
        const bool more = (t + 1 < NSTG);
        if (more) {
            const int k0 = kBase + (t + 1) * 16;
#pragma unroll
            for (int q = 0; q < 2; q++)
                aR[q] = *reinterpret_cast<const float4*>(g_xout0 + (size_t)(mBase + fam) * DOUT + k0 + fak + q * 4);
#pragma unroll
            for (int q = 0; q < 4; q++)
                bR[q] = *reinterpret_cast<const float4*>(WG + (size_t)(k0 + fbr) * DIN + nBase + (size_t)(fbn + q * 8) * 4);
        }
        {
            uint32_t ah[4][4], al[4][4], bh[4][2], bl[4][2];
#pragma unroll
            for (int mt = 0; mt < 4; mt++) {
                ldsm4(ah[mt][0], ah[mt][1], ah[mt][2], ah[mt][3],
                      smem_u32(&Ah[cur][mt * 16 + arow][acol]));
                ldsm4(al[mt][0], al[mt][1], al[mt][2], al[mt][3],
                      smem_u32(&Al[cur][mt * 16 + arow][acol]));
            }
#pragma unroll
            for (int p = 0; p < 2; p++) {
                const int bk = (g & 1) * 8 + r;
                const int bn = w * 32 + p * 16 + (g >> 1) * 8;
                ldsm4t(bh[2 * p][0], bh[2 * p][1], bh[2 * p + 1][0], bh[2 * p + 1][1],
                       smem_u32(&Bh[cur][bk][bn]));
                ldsm4t(bl[2 * p][0], bl[2 * p][1], bl[2 * p + 1][0], bl[2 * p + 1][1],
                       smem_u32(&Bl[cur][bk][bn]));
            }
#pragma unroll
            for (int mt = 0; mt < 4; mt++)
#pragma unroll
                for (int nt = 0; nt < 4; nt++) {
                    mma_bf16(c[mt][nt], ah[mt], bh[nt][0], bh[nt][1]);
                    mma_bf16(c[mt][nt], ah[mt], bl[nt][0], bl[nt][1]);
                    mma_bf16(c[mt][nt], al[mt], bh[nt][0], bh[nt][1]);
                }
        }
        if (more) {
            const int nxt = 1 - cur;
#pragma unroll
            for (int q = 0; q < 2; q++) {
                uint2 hi, lo; cvt_split(aR[q], hi, lo);
                *reinterpret_cast<uint2*>(&Ah[nxt][fam][fak + q * 4]) = hi;
                *reinterpret_cast<uint2*>(&Al[nxt][fam][fak + q * 4]) = lo;
            }
#pragma unroll
            for (int q = 0; q < 4; q++) {
                uint2 hi, lo; cvt_split(bR[q], hi, lo);
                const int n = (fbn + q * 8) * 4;
                *reinterpret_cast<uint2*>(&Bh[nxt][fbr][n]) = hi;
                *reinterpret_cast<uint2*>(&Bl[nxt][fbr][n]) = lo;
            }
        }
        __syncthreads();
    }

    float* dst = g_ppart[ks];
#pragma unroll
    for (int nt = 0; nt < 4; nt++) {
        const int n = nBase + w * 32 + nt * 8 + (lane & 3) * 2;
#pragma unroll
        for (int mt = 0; mt < 4; mt++) {
            const int m0 = mBase + mt * 16 + (lane >> 2);
            *reinterpret_cast<float2*>(dst + (size_t)m0 * DIN + n) =
                make_float2(c[mt][nt][0], c[mt][nt][1]);
            *reinterpret_cast<float2*>(dst + (size_t)(m0 + 8) * DIN + n) =
                make_float2(c[mt][nt][2], c[mt][nt][3]);
        }
    }
}

// ---------------- K4b: combine partials + bias -> g_pred ------------------
__global__ __launch_bounds__(256) void k_comb(const float* __restrict__ bG) {
    const int idx = blockIdx.x * 256 + threadIdx.x;
    const int S = BB * NOUT * DIN / 4;
    const float4* p = reinterpret_cast<const float4*>(g_ppart);
    float4 a = p[idx], b2 = p[idx + S], c2 = p[idx + 2 * S], d = p[idx + 3 * S];
    const float4 bg = reinterpret_cast<const float4*>(bG)[idx & (DIN / 4 - 1)];
    reinterpret_cast<float4*>(g_pred)[idx] = make_float4(
        a.x + b2.x + c2.x + d.x + bg.x, a.y + b2.y + c2.y + d.y + bg.y,
        a.z + b2.z + c2.z + d.z + bg.z, a.w + b2.w + c2.w + d.w + bg.w);
}

// ---------------- K5 (TENSOR, round-10 proven): S -> softmax -> phi1 ------
__global__ __launch_bounds__(128) void k_sim(const float* __restrict__ x,
                                             const float* __restrict__ bu,
                                             const float* __restrict__ bn) {
    const int i0 = blockIdx.x * 128;
    const int b = blockIdx.y;
    __shared__ __align__(16) uint16_t Ah[2][128][PKP], Al[2][128][PKP];
    __shared__ __align__(16) uint16_t Bh[2][NOUT][PKP], Bl[2][NOUT][PKP];
    const int tid = threadIdx.x, lane = tid & 31, w = tid >> 5;
    const int fbj = tid & 63, fbk = (tid >> 6) * 8;
    const int arow = lane & 15, acol = (lane >> 4) * 8;
    const int brow = ((lane >> 4) & 1) * 8 + (lane & 7), bcol = ((lane >> 3) & 1) * 8;

    const float* Arow = x + ((size_t)b * NI + i0 + tid) * DIN;
    const float* Brow = g_pred + ((size_t)b * NOUT + fbj) * DIN;

    float c[2][8][4];
#pragma unroll
    for (int mt = 0; mt < 2; mt++)
#pragma unroll
        for (int nt = 0; nt < 8; nt++)
#pragma unroll
            for (int e = 0; e < 4; e++) c[mt][nt][e] = 0.f;

    float4 aR[4]; float4 bR[2];
#pragma unroll
    for (int q = 0; q < 4; q++)
        aR[q] = *reinterpret_cast<const float4*>(Arow + q * 4);
#pragma unroll
    for (int q = 0; q < 2; q++)
        bR[q] = *reinterpret_cast<const float4*>(Brow + fbk + q * 4);
    {
#pragma unroll
        for (int q = 0; q < 4; q++) {
            uint2 hi, lo; cvt_split(aR[q], hi, lo);
            *reinterpret_cast<uint2*>(&Ah[0][tid][q * 4]) = hi;
            *reinterpret_cast<uint2*>(&Al[0][tid][q * 4]) = lo;
        }
#pragma unroll
        for (int q = 0; q < 2; q++) {
            uint2 hi, lo; cvt_split(bR[q], hi, lo);
            *reinterpret_cast<uint2*>(&Bh[0][fbj][fbk + q * 4]) = hi;
            *reinterpret_cast<uint2*>(&Bl[0][fbj][fbk + q * 4]) = lo;
        }
    }
    __syncthreads();

    const int NSTG = DIN / 16;
    for (int t = 0; t < NSTG; t++) {
        const int cur = t & 1;
        const bool more = (t + 1 < NSTG);
        if (more) {
            const int d0 = (t + 1) * 16;
#pragma unroll
            for (int q = 0; q < 4; q++)
                aR[q] = *reinterpret_cast<const float4*>(Arow + d0 + q * 4);
#pragma unroll
            for (int q = 0; q < 2; q++)
                bR[q] = *reinterpret_cast<const float4*>(Brow + d0 + fbk + q * 4);
        }
        {
            uint32_t ah[2][4], al[2][4], bh[8][2], bl[8][2];
#pragma unroll
            for (int mt = 0; mt < 2; mt++) {
                const int am = w * 32 + mt * 16 + arow;
                ldsm4(ah[mt][0], ah[mt][1], ah[mt][2], ah[mt][3],
                      smem_u32(&Ah[cur][am][acol]));
                ldsm4(al[mt][0], al[mt][1], al[mt][2], al[mt][3],
                      smem_u32(&Al[cur][am][acol]));
            }
#pragma unroll
            for (int p = 0; p < 4; p++) {
                const int bj = p * 16 + brow;
                ldsm4(bh[2 * p][0], bh[2 * p][1], bh[2 * p + 1][0], bh[2 * p + 1][1],
                      smem_u32(&Bh[cur][bj][bcol]));
                ldsm4(bl[2 * p][0], bl[2 * p][1], bl[2 * p + 1][0], bl[2 * p + 1][1],
                      smem_u32(&Bl[cur][bj][bcol]));
            }
#pragma unroll
            for (int mt = 0; mt < 2; mt++)
#pragma unroll
                for (int nt = 0; nt < 8; nt++) {
                    mma_bf16(c[mt][nt], ah[mt], bh[nt][0], bh[nt][1]);
                    mma_bf16(c[mt][nt], ah[mt], bl[nt][0], bl[nt][1]);
                    mma_bf16(c[mt][nt], al[mt], bh[nt][0], bh[nt][1]);
                }
        }
        if (more) {
            const int nxt = 1 - cur;
#pragma unroll
            for (int q = 0; q < 4; q++) {
                uint2 hi, lo; cvt_split(aR[q], hi, lo);
                *reinterpret_cast<uint2*>(&Ah[nxt][tid][q * 4]) = hi;
                *reinterpret_cast<uint2*>(&Al[nxt][tid][q * 4]) = lo;
            }
#pragma unroll
            for (int q = 0; q < 2; q++) {
                uint2 hi, lo; cvt_split(bR[q], hi, lo);
                *reinterpret_cast<uint2*>(&Bh[nxt][fbj][fbk + q * 4]) = hi;
                *reinterpret_cast<uint2*>(&Bl[nxt][fbj][fbk + q * 4]) = lo;
            }
        }
        __syncthreads();
    }

    const float scale = 0.03125f;  // 1024^-0.5
#pragma unroll
    for (int mt = 0; mt < 2; mt++) {
#pragma unroll
        for (int half = 0; half < 2; half++) {
            const int rg = i0 + w * 32 + mt * 16 + (lane >> 2) + half * 8;
            float v[16];
#pragma unroll
            for (int nt = 0; nt < 8; nt++) {
                v[nt * 2 + 0] = c[mt][nt][half * 2 + 0] * scale;
                v[nt * 2 + 1] = c[mt][nt][half * 2 + 1] * scale;
            }
            float mx = v[0];
#pragma unroll
            for (int q = 1; q < 16; q++) mx = fmaxf(mx, v[q]);
            mx = fmaxf(mx, __shfl_xor_sync(0xffffffffu, mx, 1));
            mx = fmaxf(mx, __shfl_xor_sync(0xffffffffu, mx, 2));
            float e[16], s = 0.f;
#pragma unroll
            for (int q = 0; q < 16; q++) { e[q] = __expf(v[q] - mx); s += e[q]; }
            s += __shfl_xor_sync(0xffffffffu, s, 1);
            s += __shfl_xor_sync(0xffffffffu, s, 2);
            const float inv = 1.f / s;
            const float fa = g_faT[rg * BB + b];
            float* o = g_phi1 + ((size_t)b * NI + rg) * NOUT;
#pragma unroll
            for (int nt = 0; nt < 8; nt++) {
                const int jj = nt * 8 + (lane & 3) * 2;
                const float2 bu2 = *reinterpret_cast<const float2*>(bu + (size_t)rg * NOUT + jj);
                const float2 bn2 = *reinterpret_cast<const float2*>(bn + (size_t)rg * NOUT + jj);
                *reinterpret_cast<float2*>(o + jj) = make_float2(
                    fa * ((bu2.x + bn2.x) * e[nt * 2 + 0] * inv - bn2.x),
                    fa * ((bu2.y + bn2.y) * e[nt * 2 + 1] * inv - bn2.y));
            }
        }
    }
}

// ---------------- K6: transpose phi1 [b][i][j] -> phiT [j][i][b] ----------
__global__ __launch_bounds__(256) void k_tr() {
    const int i = blockIdx.x;
    __shared__ float t[32][65];
    const int tid = threadIdx.x;
#pragma unroll
    for (int q = 0; q < 8; q++) {
        int idx = tid + q * 256;
        int bb = idx >> 6, j = idx & 63;
        t[bb][j] = g_phi1[((size_t)bb * NI + i) * NOUT + j];
    }
    __syncthreads();
#pragma unroll
    for (int q = 0; q < 8; q++) {
        int idx = tid + q * 256;
        int j = idx >> 5, bb = idx & 31;
        g_phiT[((size_t)j * NI + i) * BB + bb] = t[bb][j];
    }
}

// ---------------- launch ---------------------------------------------------
extern "C" void kernel_launch(void* const* d_in, const int* in_sizes, int n_in,
                              void* d_out, int out_size) {
    const float* x  = (const float*)d_in[0];
    const float* WA = (const float*)d_in[1];
    const float* bA = (const float*)d_in[2];
    const float* Wm = (const float*)d_in[3];
    const float* WG = (const float*)d_in[4];
    const float* bG = (const float*)d_in[5];
    const float* bu = (const float*)d_in[6];
    const float* bn = (const float*)d_in[7];
    float* out = (float*)d_out;

    k_fa<<<4096, 256>>>(x, WA, bA);
    k_phi0<<<256, 256>>>(bu, bn);
    k_mem<0><<<dim3(8, 64), 128>>>(Wm, nullptr);
    k_predp<<<dim3(8, 32, 4), 128>>>(WG);
    k_comb<<<BB * NOUT * DIN / 1024, 256>>>(bG);
    k_sim<<<dim3(8, 32), 128>>>(x, bu, bn);
    k_tr<<<NI, 256>>>();
    k_mem<1><<<dim3(8, 64), 128>>>(Wm, out);
}

// round 17
// speedup vs baseline: 1.0886x; 1.0188x over previous
#include <cuda_runtime.h>
#include <cuda_bf16.h>
#include <cstdint>

#define BB 32
#define NI 1024
#define DIN 1024
#define NOUT 64
#define DOUT 1024

// ---------------- device scratch ----------------
__device__ float g_faT[NI * BB];              // f_a transposed [i][b]
__device__ float g_xout0[BB * NOUT * DOUT];   // iter-0 output [b][j][h]
__device__ float g_pred[BB * NOUT * DIN];     // pred [b][j][d]
__device__ float g_phi1[BB * NI * NOUT];      // phi iter-1 [b][i][j]
__device__ float g_phiT[NOUT * NI * BB];      // phi transposed [j][i][b]
__device__ float g_ppart[4][BB * NOUT * DIN]; // k_pred split-K partials

// ---------------- mma helpers ----------------
__device__ __forceinline__ uint32_t smem_u32(const void* p) {
    return (uint32_t)__cvta_generic_to_shared(p);
}
__device__ __forceinline__ void ldsm4(uint32_t& r0, uint32_t& r1, uint32_t& r2,
                                      uint32_t& r3, uint32_t a) {
    asm volatile("ldmatrix.sync.aligned.m8n8.x4.shared.b16 {%0,%1,%2,%3}, [%4];"
                 : "=r"(r0), "=r"(r1), "=r"(r2), "=r"(r3) : "r"(a));
}
__device__ __forceinline__ void ldsm4t(uint32_t& r0, uint32_t& r1, uint32_t& r2,
                                       uint32_t& r3, uint32_t a) {
    asm volatile("ldmatrix.sync.aligned.m8n8.x4.trans.shared.b16 {%0,%1,%2,%3}, [%4];"
                 : "=r"(r0), "=r"(r1), "=r"(r2), "=r"(r3) : "r"(a));
}
__device__ __forceinline__ void mma_bf16(float* c, const uint32_t* a,
                                         uint32_t b0, uint32_t b1) {
    asm volatile("mma.sync.aligned.m16n8k16.row.col.f32.bf16.bf16.f32 "
                 "{%0,%1,%2,%3}, {%4,%5,%6,%7}, {%8,%9}, {%0,%1,%2,%3};"
                 : "+f"(c[0]), "+f"(c[1]), "+f"(c[2]), "+f"(c[3])
                 : "r"(a[0]), "r"(a[1]), "r"(a[2]), "r"(a[3]), "r"(b0), "r"(b1));
}
__device__ __forceinline__ uint32_t packbf(__nv_bfloat16 a, __nv_bfloat16 b) {
    return (uint32_t)__bfloat16_as_ushort(a) | ((uint32_t)__bfloat16_as_ushort(b) << 16);
}
__device__ __forceinline__ void cvt_split(float4 v, uint2& hi, uint2& lo) {
    __nv_bfloat16 hx = __float2bfloat16(v.x), hy = __float2bfloat16(v.y);
    __nv_bfloat16 hz = __float2bfloat16(v.z), hw = __float2bfloat16(v.w);
    __nv_bfloat16 lx = __float2bfloat16(v.x - __bfloat162float(hx));
    __nv_bfloat16 ly = __float2bfloat16(v.y - __bfloat162float(hy));
    __nv_bfloat16 lz = __float2bfloat16(v.z - __bfloat162float(hz));
    __nv_bfloat16 lw = __float2bfloat16(v.w - __bfloat162float(hw));
    hi.x = packbf(hx, hy); hi.y = packbf(hz, hw);
    lo.x = packbf(lx, ly); lo.y = packbf(lz, lw);
}

// ---------------- K1: f_a = sigmoid(x . W_A + b_A) -> g_faT[i][b] ---------
__global__ __launch_bounds__(256) void k_fa(const float* __restrict__ x,
                                            const float* __restrict__ WA,
                                            const float* __restrict__ bA) {
    const int row = blockIdx.x * 8 + (threadIdx.x >> 5);
    const int lane = threadIdx.x & 31;
    const float4* xr = reinterpret_cast<const float4*>(x) + (size_t)row * (DIN / 4);
    const float4* w4 = reinterpret_cast<const float4*>(WA);
    float s = 0.f;
#pragma unroll
    for (int q = 0; q < 8; q++) {
        float4 xv = xr[lane + q * 32], wv = w4[lane + q * 32];
        s += xv.x * wv.x + xv.y * wv.y + xv.z * wv.z + xv.w * wv.w;
    }
#pragma unroll
    for (int o = 16; o; o >>= 1) s += __shfl_xor_sync(0xffffffffu, s, o);
    if (lane == 0) {
        const int b = row >> 10, i = row & (NI - 1);
        float tot = s + bA[0];
        g_faT[i * BB + b] = 1.f / (1.f + __expf(-tot));
    }
}

// ---------------- K2: phi0 transposed [j][i][b] ---------------------------
__global__ __launch_bounds__(256) void k_phi0(const float* __restrict__ bu,
                                              const float* __restrict__ bn) {
    const int p = blockIdx.x * 256 + threadIdx.x;
    const int j = p >> 10, i = p & (NI - 1);
    const float cu = bu[i * NOUT + j] * (1.0f / 64.0f) - bn[i * NOUT + j] * (63.0f / 64.0f);
    const float4* fa = reinterpret_cast<const float4*>(&g_faT[i * BB]);
    float4* dst = reinterpret_cast<float4*>(&g_phiT[((size_t)j * NI + i) * BB]);
#pragma unroll
    for (int q = 0; q < 8; q++) {
        float4 v = fa[q];
        dst[q] = make_float4(v.x * cu, v.y * cu, v.z * cu, v.w * cu);
    }
}

// ---------------- K3 (TENSOR): out = phiT . Wm  (row-per-warp B staging) --
// Grid (hb 0..7, j 0..63), 128 thr. Tile 32b x 128h, stage K=32.
// B: one full row per warp per q (32 lanes x 16B LDG, 256B contiguous STS).
#define AMP 40
#define BNP 136
template <int MODE>
__global__ __launch_bounds__(128) void k_mem(const float* __restrict__ Wm,
                                             float* __restrict__ outp) {
    const int j = blockIdx.y, hb = blockIdx.x;
    __shared__ __align__(16) uint16_t Ah[2][32][AMP], Al[2][32][AMP];
    __shared__ __align__(16) uint16_t Bh[2][32][BNP], Bl[2][32][BNP];
    const int tid = threadIdx.x, lane = tid & 31, w = tid >> 5;
    const int far_ = tid >> 2, fac = (tid & 3) * 8; // A: rows 0..31, 2 f4
    const int g = lane >> 3, r = lane & 7;
    const float* WmB = Wm + (size_t)j * DOUT + (size_t)hb * 128;
    const float* Ab = g_phiT + (size_t)j * (NI * BB);

    float c[2][4][4];
#pragma unroll
    for (int mt = 0; mt < 2; mt++)
#pragma unroll
        for (int nt = 0; nt < 4; nt++)
#pragma unroll
            for (int e = 0; e < 4; e++) c[mt][nt][e] = 0.f;

    float4 bR[8], aR[2];
    {
#pragma unroll
        for (int q = 0; q < 8; q++)
            bR[q] = *reinterpret_cast<const float4*>(
                WmB + (size_t)(w * 8 + q) * (NOUT * DOUT) + lane * 4);
        const float* ar = Ab + (size_t)far_ * BB + fac;
        aR[0] = *reinterpret_cast<const float4*>(ar);
        aR[1] = *reinterpret_cast<const float4*>(ar + 4);
    }
    {
#pragma unroll
        for (int q = 0; q < 8; q++) {
            uint2 hi, lo; cvt_split(bR[q], hi, lo);
            *reinterpret_cast<uint2*>(&Bh[0][w * 8 + q][lane * 4]) = hi;
            *reinterpret_cast<uint2*>(&Bl[0][w * 8 + q][lane * 4]) = lo;
        }
        uint2 h0, l0, h1, l1;
        cvt_split(aR[0], h0, l0); cvt_split(aR[1], h1, l1);
        *reinterpret_cast<uint4*>(&Ah[0][far_][fac]) = make_uint4(h0.x, h0.y, h1.x, h1.y);
        *reinterpret_cast<uint4*>(&Al[0][far_][fac]) = make_uint4(l0.x, l0.y, l1.x, l1.y);
    }
    __syncthreads();

    const int NSTG = NI / 32;
    for (int t = 0; t < NSTG; t++) {
        const int cur = t & 1;
        const bool more = (t + 1 < NSTG);
        if (more) {
            const int i0 = (t + 1) * 32;
#pragma unroll
            for (int q = 0; q < 8; q++)
                bR[q] = *reinterpret_cast<const float4*>(
                    WmB + (size_t)(i0 + w * 8 + q) * (NOUT * DOUT) + lane * 4);
            const float* ar = Ab + (size_t)(i0 + far_) * BB + fac;
            aR[0] = *reinterpret_cast<const float4*>(ar);
            aR[1] = *reinterpret_cast<const float4*>(ar + 4);
        }
#pragma unroll
        for (int kk = 0; kk < 32; kk += 16) {
            uint32_t ah[2][4], al[2][4], bh[4][2], bl[4][2];
#pragma unroll
            for (int mt = 0; mt < 2; mt++) {
                const int ak = kk + (g >> 1) * 8 + r, am = mt * 16 + (g & 1) * 8;
                ldsm4t(ah[mt][0], ah[mt][1], ah[mt][2], ah[mt][3],
                       smem_u32(&Ah[cur][ak][am]));
                ldsm4t(al[mt][0], al[mt][1], al[mt][2], al[mt][3],
                       smem_u32(&Al[cur][ak][am]));
            }
#pragma unroll
            for (int p = 0; p < 2; p++) {
                const int bk = kk + (g & 1) * 8 + r;
                const int bn = w * 32 + p * 16 + (g >> 1) * 8;
                ldsm4t(bh[2 * p][0], bh[2 * p][1], bh[2 * p + 1][0], bh[2 * p + 1][1],
                       smem_u32(&Bh[cur][bk][bn]));
                ldsm4t(bl[2 * p][0], bl[2 * p][1], bl[2 * p + 1][0], bl[2 * p + 1][1],
                       smem_u32(&Bl[cur][bk][bn]));
            }
#pragma unroll
            for (int mt = 0; mt < 2; mt++)
#pragma unroll
                for (int nt = 0; nt < 4; nt++) {
                    mma_bf16(c[mt][nt], ah[mt], bh[nt][0], bh[nt][1]);
                    mma_bf16(c[mt][nt], ah[mt], bl[nt][0], bl[nt][1]);
                    mma_bf16(c[mt][nt], al[mt], bh[nt][0], bh[nt][1]);
                }
        }
        if (more) {
            const int nxt = 1 - cur;
#pragma unroll
            for (int q = 0; q < 8; q++) {
                uint2 hi, lo; cvt_split(bR[q], hi, lo);
                *reinterpret_cast<uint2*>(&Bh[nxt][w * 8 + q][lane * 4]) = hi;
                *reinterpret_cast<uint2*>(&Bl[nxt][w * 8 + q][lane * 4]) = lo;
            }
            uint2 h0, l0, h1, l1;
            cvt_split(aR[0], h0, l0); cvt_split(aR[1], h1, l1);
            *reinterpret_cast<uint4*>(&Ah[nxt][far_][fac]) = make_uint4(h0.x, h0.y, h1.x, h1.y);
            *reinterpret_cast<uint4*>(&Al[nxt][far_][fac]) = make_uint4(l0.x, l0.y, l1.x, l1.y);
        }
        __syncthreads();
    }

    float* dst = (MODE == 0) ? g_xout0 : outp;
#pragma unroll
    for (int mt = 0; mt < 2; mt++)
#pragma unroll
        for (int nt = 0; nt < 4; nt++) {
            const int m0 = mt * 16 + (lane >> 2);
            const int n = hb * 128 + w * 32 + nt * 8 + (lane & 3) * 2;
            float* o0 = dst + ((size_t)(m0 * NOUT + j)) * DOUT + n;
            *reinterpret_cast<float2*>(o0) = make_float2(c[mt][nt][0], c[mt][nt][1]);
            float* o1 = dst + ((size_t)((m0 + 8) * NOUT + j)) * DOUT + n;
            *reinterpret_cast<float2*>(o1) = make_float2(c[mt][nt][2], c[mt][nt][3]);
        }
}

// ---------------- K4 (TENSOR, split-K): pred partials ---------------------
// B staging: one full row per warp per q (zero-conflict STS).
#define PKP 24
__global__ __launch_bounds__(128) void k_predp(const float* __restrict__ WG) {
    const int nb = blockIdx.x, mb = blockIdx.y, ks = blockIdx.z;
    const int mBase = mb * 64, nBase = nb * 128, kBase = ks * 256;
    __shared__ __align__(16) uint16_t Ah[2][64][PKP], Al[2][64][PKP];
    __shared__ __align__(16) uint16_t Bh[2][16][BNP], Bl[2][16][BNP];
    const int tid = threadIdx.x, lane = tid & 31, w = tid >> 5;
    const int g = lane >> 3, r = lane & 7;
    const int fam = tid & 63, fak = (tid >> 6) * 8;
    const int arow = lane & 15, acol = (lane >> 4) * 8;

    float c[4][4][4];
#pragma unroll
    for (int mt = 0; mt < 4; mt++)
#pragma unroll
        for (int nt = 0; nt < 4; nt++)
#pragma unroll
            for (int e = 0; e < 4; e++) c[mt][nt][e] = 0.f;

    float4 aR[2], bR[4];
#pragma unroll
    for (int q = 0; q < 2; q++)
        aR[q] = *reinterpret_cast<const float4*>(g_xout0 + (size_t)(mBase + fam) * DOUT + kBase + fak + q * 4);
#pragma unroll
    for (int q = 0; q < 4; q++)
        bR[q] = *reinterpret_cast<const float4*>(WG + (size_t)(kBase + w * 4 + q) * DIN + nBase + lane * 4);
    {
#pragma unroll
        for (int q = 0; q < 2; q++) {
            uint2 hi, lo; cvt_split(aR[q], hi, lo);
            *reinterpret_cast<uint2*>(&Ah[0][fam][fak + q * 4]) = hi;
            *reinterpret_cast<uint2*>(&Al[0][fam][fak + q * 4]) = lo;
        }
#pragma unroll
        for (int q = 0; q < 4; q++) {
            uint2 hi, lo; cvt_split(bR[q], hi, lo);
            *reinterpret_cast<uint2*>(&Bh[0][w * 4 + q][lane * 4]) = hi;
            *reinterpret_cast<uint2*>(&Bl[0][w * 4 + q][lane * 4]) = lo;
        }
    }
    __syncthreads();

    const int NSTG = 256 / 16;
    for (int t = 0; t < NSTG; t++) {
        const int cur = t & 1;
        const bool more = (t + 1 < NSTG);
        if (more) {
            const int k0 = kBase + (t + 1) * 16;
#pragma unroll
            for (int q = 0; q < 2; q++)
                aR[q] = *reinterpret_cast<const float4*>(g_xout0 + (size_t)(mBase + fam) * DOUT + k0 + fak + q * 4);
#pragma unroll
            for (int q = 0; q < 4; q++)
                bR[q] = *reinterpret_cast<const float4*>(WG + (size_t)(k0 + w * 4 + q) * DIN + nBase + lane * 4);
        }
        {
            uint32_t ah[4][4], al[4][4], bh[4][2], bl[4][2];
#pragma unroll
            for (int mt = 0; mt < 4; mt++) {
                ldsm4(ah[mt][0], ah[mt][1], ah[mt][2], ah[mt][3],
                      smem_u32(&Ah[cur][mt * 16 + arow][acol]));
                ldsm4(al[mt][0], al[mt][1], al[mt][2], al[mt][3],
                      smem_u32(&Al[cur][mt * 16 + arow][acol]));
            }
#pragma unroll
            for (int p = 0; p < 2; p++) {
                const int bk = (g & 1) * 8 + r;
                const int bn = w * 32 + p * 16 + (g >> 1) * 8;
                ldsm4t(bh[2 * p][0], bh[2 * p][1], bh[2 * p + 1][0], bh[2 * p + 1][1],
                       smem_u32(&Bh[cur][bk][bn]));
                ldsm4t(bl[2 * p][0], bl[2 * p][1], bl[2 * p + 1][0], bl[2 * p + 1][1],
                       smem_u32(&Bl[cur][bk][bn]));
            }
#pragma unroll
            for (int mt = 0; mt < 4; mt++)
#pragma unroll
                for (int nt = 0; nt < 4; nt++) {
                    mma_bf16(c[mt][nt], ah[mt], bh[nt][0], bh[nt][1]);
                    mma_bf16(c[mt][nt], ah[mt], bl[nt][0], bl[nt][1]);
                    mma_bf16(c[mt][nt], al[mt], bh[nt][0], bh[nt][1]);
                }
        }
        if (more) {
            const int nxt = 1 - cur;
#pragma unroll
            for (int q = 0; q < 2; q++) {
                uint2 hi, lo; cvt_split(aR[q], hi, lo);
                *reinterpret_cast<uint2*>(&Ah[nxt][fam][fak + q * 4]) = hi;
                *reinterpret_cast<uint2*>(&Al[nxt][fam][fak + q * 4]) = lo;
            }
#pragma unroll
            for (int q = 0; q < 4; q++) {
                uint2 hi, lo; cvt_split(bR[q], hi, lo);
                *reinterpret_cast<uint2*>(&Bh[nxt][w * 4 + q][lane * 4]) = hi;
                *reinterpret_cast<uint2*>(&Bl[nxt][w * 4 + q][lane * 4]) = lo;
            }
        }
        __syncthreads();
    }

    float* dst = g_ppart[ks];
#pragma unroll
    for (int nt = 0; nt < 4; nt++) {
        const int n = nBase + w * 32 + nt * 8 + (lane & 3) * 2;
#pragma unroll
        for (int mt = 0; mt < 4; mt++) {
            const int m0 = mBase + mt * 16 + (lane >> 2);
            *reinterpret_cast<float2*>(dst + (size_t)m0 * DIN + n) =
                make_float2(c[mt][nt][0], c[mt][nt][1]);
            *reinterpret_cast<float2*>(dst + (size_t)(m0 + 8) * DIN + n) =
                make_float2(c[mt][nt][2], c[mt][nt][3]);
        }
    }
}

// ---------------- K4b: combine partials + bias -> g_pred ------------------
__global__ __launch_bounds__(256) void k_comb(const float* __restrict__ bG) {
    const int idx = blockIdx.x * 256 + threadIdx.x;
    const int S = BB * NOUT * DIN / 4;
    const float4* p = reinterpret_cast<const float4*>(g_ppart);
    float4 a = p[idx], b2 = p[idx + S], c2 = p[idx + 2 * S], d = p[idx + 3 * S];
    const float4 bg = reinterpret_cast<const float4*>(bG)[idx & (DIN / 4 - 1)];
    reinterpret_cast<float4*>(g_pred)[idx] = make_float4(
        a.x + b2.x + c2.x + d.x + bg.x, a.y + b2.y + c2.y + d.y + bg.y,
        a.z + b2.z + c2.z + d.z + bg.z, a.w + b2.w + c2.w + d.w + bg.w);
}

// ---------------- K5 (TENSOR, round-10 proven): S -> softmax -> phi1 ------
__global__ __launch_bounds__(128) void k_sim(const float* __restrict__ x,
                                             const float* __restrict__ bu,
                                             const float* __restrict__ bn) {
    const int i0 = blockIdx.x * 128;
    const int b = blockIdx.y;
    __shared__ __align__(16) uint16_t Ah[2][128][PKP], Al[2][128][PKP];
    __shared__ __align__(16) uint16_t Bh[2][NOUT][PKP], Bl[2][NOUT][PKP];
    const int tid = threadIdx.x, lane = tid & 31, w = tid >> 5;
    const int fbj = tid & 63, fbk = (tid >> 6) * 8;
    const int arow = lane & 15, acol = (lane >> 4) * 8;
    const int brow = ((lane >> 4) & 1) * 8 + (lane & 7), bcol = ((lane >> 3) & 1) * 8;

    const float* Arow = x + ((size_t)b * NI + i0 + tid) * DIN;
    const float* Brow = g_pred + ((size_t)b * NOUT + fbj) * DIN;

    float c[2][8][4];
#pragma unroll
    for (int mt = 0; mt < 2; mt++)
#pragma unroll
        for (int nt = 0; nt < 8; nt++)
#pragma unroll
            for (int e = 0; e < 4; e++) c[mt][nt][e] = 0.f;

    float4 aR[4]; float4 bR[2];
#pragma unroll
    for (int q = 0; q < 4; q++)
        aR[q] = *reinterpret_cast<const float4*>(Arow + q * 4);
#pragma unroll
    for (int q = 0; q < 2; q++)
        bR[q] = *reinterpret_cast<const float4*>(Brow + fbk + q * 4);
    {
#pragma unroll
        for (int q = 0; q < 4; q++) {
            uint2 hi, lo; cvt_split(aR[q], hi, lo);
            *reinterpret_cast<uint2*>(&Ah[0][tid][q * 4]) = hi;
            *reinterpret_cast<uint2*>(&Al[0][tid][q * 4]) = lo;
        }
#pragma unroll
        for (int q = 0; q < 2; q++) {
            uint2 hi, lo; cvt_split(bR[q], hi, lo);
            *reinterpret_cast<uint2*>(&Bh[0][fbj][fbk + q * 4]) = hi;
            *reinterpret_cast<uint2*>(&Bl[0][fbj][fbk + q * 4]) = lo;
        }
    }
    __syncthreads();

    const int NSTG = DIN / 16;
    for (int t = 0; t < NSTG; t++) {
        const int cur = t & 1;
        const bool more = (t + 1 < NSTG);
        if (more) {
            const int d0 = (t + 1) * 16;
#pragma unroll
            for (int q = 0; q < 4; q++)
                aR[q] = *reinterpret_cast<const float4*>(Arow + d0 + q * 4);
#pragma unroll
            for (int q = 0; q < 2; q++)
                bR[q] = *reinterpret_cast<const float4*>(Brow + d0 + fbk + q * 4);
        }
        {
            uint32_t ah[2][4], al[2][4], bh[8][2], bl[8][2];
#pragma unroll
            for (int mt = 0; mt < 2; mt++) {
                const int am = w * 32 + mt * 16 + arow;
                ldsm4(ah[mt][0], ah[mt][1], ah[mt][2], ah[mt][3],
                      smem_u32(&Ah[cur][am][acol]));
                ldsm4(al[mt][0], al[mt][1], al[mt][2], al[mt][3],
                      smem_u32(&Al[cur][am][acol]));
            }
#pragma unroll
            for (int p = 0; p < 4; p++) {
                const int bj = p * 16 + brow;
                ldsm4(bh[2 * p][0], bh[2 * p][1], bh[2 * p + 1][0], bh[2 * p + 1][1],
                      smem_u32(&Bh[cur][bj][bcol]));
                ldsm4(bl[2 * p][0], bl[2 * p][1], bl[2 * p + 1][0], bl[2 * p + 1][1],
                      smem_u32(&Bl[cur][bj][bcol]));
            }
#pragma unroll
            for (int mt = 0; mt < 2; mt++)
#pragma unroll
                for (int nt = 0; nt < 8; nt++) {
                    mma_bf16(c[mt][nt], ah[mt], bh[nt][0], bh[nt][1]);
                    mma_bf16(c[mt][nt], ah[mt], bl[nt][0], bl[nt][1]);
                    mma_bf16(c[mt][nt], al[mt], bh[nt][0], bh[nt][1]);
                }
        }
        if (more) {
            const int nxt = 1 - cur;
#pragma unroll
            for (int q = 0; q < 4; q++) {
                uint2 hi, lo; cvt_split(aR[q], hi, lo);
                *reinterpret_cast<uint2*>(&Ah[nxt][tid][q * 4]) = hi;
                *reinterpret_cast<uint2*>(&Al[nxt][tid][q * 4]) = lo;
            }
#pragma unroll
            for (int q = 0; q < 2; q++) {
                uint2 hi, lo; cvt_split(bR[q], hi, lo);
                *reinterpret_cast<uint2*>(&Bh[nxt][fbj][fbk + q * 4]) = hi;
                *reinterpret_cast<uint2*>(&Bl[nxt][fbj][fbk + q * 4]) = lo;
            }
        }
        __syncthreads();
    }

    const float scale = 0.03125f;  // 1024^-0.5
#pragma unroll
    for (int mt = 0; mt < 2; mt++) {
#pragma unroll
        for (int half = 0; half < 2; half++) {
            const int rg = i0 + w * 32 + mt * 16 + (lane >> 2) + half * 8;
            float v[16];
#pragma unroll
            for (int nt = 0; nt < 8; nt++) {
                v[nt * 2 + 0] = c[mt][nt][half * 2 + 0] * scale;
                v[nt * 2 + 1] = c[mt][nt][half * 2 + 1] * scale;
            }
            float mx = v[0];
#pragma unroll
            for (int q = 1; q < 16; q++) mx = fmaxf(mx, v[q]);
            mx = fmaxf(mx, __shfl_xor_sync(0xffffffffu, mx, 1));
            mx = fmaxf(mx, __shfl_xor_sync(0xffffffffu, mx, 2));
            float e[16], s = 0.f;
#pragma unroll
            for (int q = 0; q < 16; q++) { e[q] = __expf(v[q] - mx); s += e[q]; }
            s += __shfl_xor_sync(0xffffffffu, s, 1);
            s += __shfl_xor_sync(0xffffffffu, s, 2);
            const float inv = 1.f / s;
            const float fa = g_faT[rg * BB + b];
            float* o = g_phi1 + ((size_t)b * NI + rg) * NOUT;
#pragma unroll
            for (int nt = 0; nt < 8; nt++) {
                const int jj = nt * 8 + (lane & 3) * 2;
                const float2 bu2 = *reinterpret_cast<const float2*>(bu + (size_t)rg * NOUT + jj);
                const float2 bn2 = *reinterpret_cast<const float2*>(bn + (size_t)rg * NOUT + jj);
                *reinterpret_cast<float2*>(o + jj) = make_float2(
                    fa * ((bu2.x + bn2.x) * e[nt * 2 + 0] * inv - bn2.x),
                    fa * ((bu2.y + bn2.y) * e[nt * 2 + 1] * inv - bn2.y));
            }
        }
    }
}

// ---------------- K6: transpose phi1 [b][i][j] -> phiT [j][i][b] ----------
__global__ __launch_bounds__(256) void k_tr() {
    const int i = blockIdx.x;
    __shared__ float t[32][65];
    const int tid = threadIdx.x;
#pragma unroll
    for (int q = 0; q < 8; q++) {
        int idx = tid + q * 256;
        int bb = idx >> 6, j = idx & 63;
        t[bb][j] = g_phi1[((size_t)bb * NI + i) * NOUT + j];
    }
    __syncthreads();
#pragma unroll
    for (int q = 0; q < 8; q++) {
        int idx = tid + q * 256;
        int j = idx >> 5, bb = idx & 31;
        g_phiT[((size_t)j * NI + i) * BB + bb] = t[bb][j];
    }
}

// ---------------- launch ---------------------------------------------------
extern "C" void kernel_launch(void* const* d_in, const int* in_sizes, int n_in,
                              void* d_out, int out_size) {
    const float* x  = (const float*)d_in[0];
    const float* WA = (const float*)d_in[1];
    const float* bA = (const float*)d_in[2];
    const float* Wm = (const float*)d_in[3];
    const float* WG = (const float*)d_in[4];
    const float* bG = (const float*)d_in[5];
    const float* bu = (const float*)d_in[6];
    const float* bn = (const float*)d_in[7];
    float* out = (float*)d_out;

    k_fa<<<4096, 256>>>(x, WA, bA);
    k_phi0<<<256, 256>>>(bu, bn);
    k_mem<0><<<dim3(8, 64), 128>>>(Wm, nullptr);
    k_predp<<<dim3(8, 32, 4), 128>>>(WG);
    k_comb<<<BB * NOUT * DIN / 1024, 256>>>(bG);
    k_sim<<<dim3(8, 32), 128>>>(x, bu, bn);
    k_tr<<<NI, 256>>>();
    k_mem<1><<<dim3(8, 64), 128>>>(Wm, out);
}